// round 7
// baseline (speedup 1.0000x reference)
#include <cuda_runtime.h>
#include <cuda_bf16.h>
#include <cstdint>

#define BB 2
#define CC 1024
#define TT 2048
#define HH 16
#define DH 64
#define LN_EPS 1e-6f

// ---- dense GEMM tiling: 128x128 tile, KC=16, 4-stage cp.async pipeline ----
#define GM_MT 128
#define GM_NT 128
#define GM_KC 16
#define NCHUNK (CC / GM_KC)            // 64
#define PITCH 24                        // 16 bf16 + 8 pad
#define A_BYTES (GM_MT * PITCH * 2)     // 6144
#define B_BYTES (GM_NT * PITCH * 2)     // 6144
#define STAGE_BYTES (2 * A_BYTES + 2 * B_BYTES)  // 24576
#define GEMM_SMEM (4 * STAGE_BYTES)     // 98304 -> 2 CTAs/SM

// ---- attention tiling ----
#define QPITCH 72
#define VPITCH 136
#define AQ_B (128 * QPITCH * 2)
#define AV_B (64 * VPITCH * 2)
#define ASTAGE_B (2 * AQ_B + 2 * AV_B)
#define ATTN_SMEM (2 * AQ_B + 2 * ASTAGE_B)      // 180224

// ---- scratch ----
__device__ float g_y[(size_t)BB * CC * TT];
__device__ __nv_bfloat16 g_wqkv_hi[3 * CC * CC], g_wqkv_lo[3 * CC * CC];
__device__ __nv_bfloat16 g_wfc_hi[CC * CC], g_wfc_lo[CC * CC];
__device__ __nv_bfloat16 g_xT_hi[(size_t)BB * TT * CC], g_xT_lo[(size_t)BB * TT * CC];
__device__ __nv_bfloat16 g_cT_hi[(size_t)BB * TT * CC], g_cT_lo[(size_t)BB * TT * CC];
__device__ __nv_bfloat16 g_qT_hi[(size_t)BB * HH * TT * DH], g_qT_lo[(size_t)BB * HH * TT * DH];
__device__ __nv_bfloat16 g_kT_hi[(size_t)BB * HH * TT * DH], g_kT_lo[(size_t)BB * HH * TT * DH];
__device__ __nv_bfloat16 g_v_hi[(size_t)BB * HH * DH * TT], g_v_lo[(size_t)BB * HH * DH * TT];

// ===========================================================================
__device__ __forceinline__ uint32_t smem_u32(const void* p) {
    return (uint32_t)__cvta_generic_to_shared(p);
}
__device__ __forceinline__ void cp16(uint32_t dst, const void* src) {
    asm volatile("cp.async.cg.shared.global [%0], [%1], 16;\n" :: "r"(dst), "l"(src));
}
__device__ __forceinline__ void cp_commit() {
    asm volatile("cp.async.commit_group;\n" ::: "memory");
}
__device__ __forceinline__ void ldmatrix_x4(uint32_t& a0, uint32_t& a1, uint32_t& a2,
                                            uint32_t& a3, uint32_t addr) {
    asm volatile("ldmatrix.sync.aligned.m8n8.x4.shared.b16 {%0,%1,%2,%3}, [%4];"
                 : "=r"(a0), "=r"(a1), "=r"(a2), "=r"(a3) : "r"(addr));
}
__device__ __forceinline__ void mma_bf16(float* c,
                                         uint32_t a0, uint32_t a1, uint32_t a2, uint32_t a3,
                                         uint32_t b0, uint32_t b1) {
    asm volatile(
        "mma.sync.aligned.m16n8k16.row.col.f32.bf16.bf16.f32 "
        "{%0,%1,%2,%3}, {%4,%5,%6,%7}, {%8,%9}, {%0,%1,%2,%3};"
        : "+f"(c[0]), "+f"(c[1]), "+f"(c[2]), "+f"(c[3])
        : "r"(a0), "r"(a1), "r"(a2), "r"(a3), "r"(b0), "r"(b1));
}
__device__ __forceinline__ uint32_t cvt2(float f0, float f1) {
    uint32_t r;
    asm("cvt.rn.bf16x2.f32 %0, %1, %2;" : "=r"(r) : "f"(f1), "f"(f0));
    return r;
}
__device__ __forceinline__ void split2(float f0, float f1, uint32_t& hi, uint32_t& lo) {
    hi = cvt2(f0, f1);
    const float h0 = __uint_as_float(hi << 16);
    const float h1 = __uint_as_float(hi & 0xffff0000u);
    lo = cvt2(f0 - h0, f1 - h1);
}

// ===========================================================================
// conversions
// ===========================================================================
__global__ void __launch_bounds__(256) split_kernel(
    const float* __restrict__ in, __nv_bfloat16* __restrict__ hi,
    __nv_bfloat16* __restrict__ lo, int n)
{
    int i = blockIdx.x * 256 + threadIdx.x;
    if (i < n) {
        const float v = in[i];
        const __nv_bfloat16 h = __float2bfloat16(v);
        hi[i] = h;
        lo[i] = __float2bfloat16(v - __bfloat162float(h));
    }
}

__global__ void __launch_bounds__(256) tsplit_kernel(
    const float* __restrict__ in, __nv_bfloat16* __restrict__ hi,
    __nv_bfloat16* __restrict__ lo)
{
    __shared__ float tile[32][33];
    const int b = blockIdx.z;
    const int t0 = blockIdx.x * 32, c0 = blockIdx.y * 32;
    const float* ib = in + (size_t)b * CC * TT;
    for (int j = threadIdx.y; j < 32; j += 8)
        tile[j][threadIdx.x] = ib[(size_t)(c0 + j) * TT + t0 + threadIdx.x];
    __syncthreads();
    __nv_bfloat16* hb = hi + (size_t)b * TT * CC;
    __nv_bfloat16* lb = lo + (size_t)b * TT * CC;
    for (int j = threadIdx.y; j < 32; j += 8) {
        const float v = tile[threadIdx.x][j];
        const __nv_bfloat16 h = __float2bfloat16(v);
        const size_t o = (size_t)(t0 + j) * CC + c0 + threadIdx.x;
        hb[o] = h;
        lb[o] = __float2bfloat16(v - __bfloat162float(h));
    }
}

// ===========================================================================
// mma.sync bf16-split GEMM; 4-stage pipeline (prefetch distance 3, 2 CTAs/SM)
// EPI: 1 = +residual -> fp32 Cout, 2 = QKV split epilogue
// ===========================================================================
__device__ __forceinline__ void g_load_stage(
    uint32_t st, int kc,
    const __nv_bfloat16* __restrict__ Ahi, const __nv_bfloat16* __restrict__ Alo,
    const __nv_bfloat16* __restrict__ Bhi, const __nv_bfloat16* __restrict__ Blo,
    int m0, int n0, int tid)
{
    // A: 128 rows x 2 x 16B per hi/lo; one iter per thread
    {
        const int r = tid >> 1, c = tid & 1;
        const uint32_t dst = st + (uint32_t)(r * PITCH + c * 8) * 2;
        const size_t g = (size_t)(m0 + r) * CC + kc + c * 8;
        cp16(dst, Ahi + g);
        cp16(dst + A_BYTES, Alo + g);
    }
    {
        const int r = tid >> 1, c = tid & 1;
        const uint32_t dst = st + 2 * A_BYTES + (uint32_t)(r * PITCH + c * 8) * 2;
        const size_t g = (size_t)(n0 + r) * CC + kc + c * 8;
        cp16(dst, Bhi + g);
        cp16(dst + B_BYTES, Blo + g);
    }
}

template <int EPI>
__global__ void __launch_bounds__(256) hgemm(
    const __nv_bfloat16* __restrict__ Ahi, const __nv_bfloat16* __restrict__ Alo,
    const __nv_bfloat16* __restrict__ BhiAll, const __nv_bfloat16* __restrict__ BloAll,
    const float* __restrict__ Res, float* __restrict__ Cout, long outBatchStride)
{
    extern __shared__ char smem[];
    const uint32_t sbase = smem_u32(smem);

    const int tid = threadIdx.x;
    const int wid = tid >> 5;
    const int lane = tid & 31;
    const int b = blockIdx.z;
    const int m0 = blockIdx.y * GM_MT;
    const int n0 = blockIdx.x * GM_NT;
    const int wm = (wid >> 2) * 64;
    const int wn = (wid & 3) * 32;

    const __nv_bfloat16* Bhi = BhiAll + (size_t)b * TT * CC;
    const __nv_bfloat16* Blo = BloAll + (size_t)b * TT * CC;

    float acc[4][4][4];
#pragma unroll
    for (int i = 0; i < 4; i++)
#pragma unroll
        for (int j = 0; j < 4; j++)
#pragma unroll
            for (int r = 0; r < 4; r++) acc[i][j][r] = 0.0f;

    const int a_row = lane & 15;
    const int a_ksel = (lane >> 4) * 8;
    const int b4_row = lane & 7;
    const int b4_k = ((lane >> 3) & 1) * 8;
    const int b4_n = ((lane >> 4) & 1) * 8;

    // prologue: stages 0,1,2
#pragma unroll
    for (int s = 0; s < 3; s++) {
        g_load_stage(sbase + (uint32_t)s * STAGE_BYTES, s * GM_KC,
                     Ahi, Alo, Bhi, Blo, m0, n0, tid);
        cp_commit();
    }

    for (int c = 0; c < NCHUNK; c++) {
        // chunk c was commit #c+1; commits issued so far = c+3 -> allow 2 pending
        asm volatile("cp.async.wait_group 2;\n" ::: "memory");
        __syncthreads();
        if (c + 3 < NCHUNK)
            g_load_stage(sbase + (uint32_t)((c + 3) & 3) * STAGE_BYTES,
                         (c + 3) * GM_KC, Ahi, Alo, Bhi, Blo, m0, n0, tid);
        cp_commit();  // uniform commit keeps group arithmetic constant

        const uint32_t st = sbase + (uint32_t)(c & 3) * STAGE_BYTES;
        const uint32_t sAh = st;
        const uint32_t sAl = st + A_BYTES;
        const uint32_t sBh = st + 2 * A_BYTES;
        const uint32_t sBl = st + 2 * A_BYTES + B_BYTES;

        uint32_t ah[4][4], al[4][4], bh[4][2], bl[4][2];
#pragma unroll
        for (int mi = 0; mi < 4; mi++) {
            const uint32_t off =
                (uint32_t)((wm + mi * 16 + a_row) * PITCH + a_ksel) * 2;
            ldmatrix_x4(ah[mi][0], ah[mi][1], ah[mi][2], ah[mi][3], sAh + off);
            ldmatrix_x4(al[mi][0], al[mi][1], al[mi][2], al[mi][3], sAl + off);
        }
#pragma unroll
        for (int p = 0; p < 2; p++) {
            const uint32_t off =
                (uint32_t)((wn + p * 16 + b4_n + b4_row) * PITCH + b4_k) * 2;
            ldmatrix_x4(bh[2 * p][0], bh[2 * p][1], bh[2 * p + 1][0],
                        bh[2 * p + 1][1], sBh + off);
            ldmatrix_x4(bl[2 * p][0], bl[2 * p][1], bl[2 * p + 1][0],
                        bl[2 * p + 1][1], sBl + off);
        }
#pragma unroll
        for (int mi = 0; mi < 4; mi++)
#pragma unroll
            for (int nj = 0; nj < 4; nj++) {
                float* a = acc[mi][nj];
                mma_bf16(a, ah[mi][0], ah[mi][1], ah[mi][2], ah[mi][3],
                         bh[nj][0], bh[nj][1]);
                mma_bf16(a, ah[mi][0], ah[mi][1], ah[mi][2], ah[mi][3],
                         bl[nj][0], bl[nj][1]);
                mma_bf16(a, al[mi][0], al[mi][1], al[mi][2], al[mi][3],
                         bh[nj][0], bh[nj][1]);
            }
        // no trailing sync: stage (c+4)%4 loaded next iter is disjoint from
        // stages c+1..c+3 in flight; next-iter sync precedes its load issue.
    }
    __syncthreads();

    const int er = lane >> 2;
    const int ec = (lane & 3) * 2;

    if (EPI == 1) {
        float* Cb = Cout + (size_t)b * outBatchStride;
        const float* Rb = Res + (size_t)b * CC * TT;
#pragma unroll
        for (int mi = 0; mi < 4; mi++)
#pragma unroll
            for (int nj = 0; nj < 4; nj++) {
                const int m = m0 + wm + mi * 16 + er;
                const int n = n0 + wn + nj * 8 + ec;
                float2 v0 = make_float2(acc[mi][nj][0], acc[mi][nj][1]);
                float2 v1 = make_float2(acc[mi][nj][2], acc[mi][nj][3]);
                const float2 r0 = *(const float2*)(Rb + (size_t)m * TT + n);
                const float2 r1 = *(const float2*)(Rb + (size_t)(m + 8) * TT + n);
                v0.x += r0.x; v0.y += r0.y;
                v1.x += r1.x; v1.y += r1.y;
                *(float2*)(Cb + (size_t)m * TT + n) = v0;
                *(float2*)(Cb + (size_t)(m + 8) * TT + n) = v1;
            }
    } else {
        // EPI == 2: QKV epilogue, write attention operand layouts directly
        if (m0 >= 2 * CC) {
            const int chBase = m0 - 2 * CC;
            uint32_t* vhi = (uint32_t*)g_v_hi;
            uint32_t* vlo = (uint32_t*)g_v_lo;
#pragma unroll
            for (int mi = 0; mi < 4; mi++)
#pragma unroll
                for (int nj = 0; nj < 4; nj++) {
                    const int n = n0 + wn + nj * 8 + ec;
#pragma unroll
                    for (int rr = 0; rr < 2; rr++) {
                        const int ch = chBase + wm + mi * 16 + er + rr * 8;
                        const int bh = b * HH + (ch >> 6);
                        const int d = ch & 63;
                        uint32_t hi, lo;
                        split2(acc[mi][nj][2 * rr], acc[mi][nj][2 * rr + 1], hi, lo);
                        const size_t idx = (((size_t)bh * DH + d) * TT + n) >> 1;
                        vhi[idx] = hi;
                        vlo[idx] = lo;
                    }
                }
        } else {
            const bool isK = (m0 >= CC);
            const int chBase = isK ? (m0 - CC) : m0;
            const int h0 = chBase >> 6;
            float* stg = (float*)smem;  // [n(128)][m(128)] pitch 129 (66048 B)
#pragma unroll
            for (int mi = 0; mi < 4; mi++)
#pragma unroll
                for (int nj = 0; nj < 4; nj++) {
                    const int m = wm + mi * 16 + er;
                    const int n = wn + nj * 8 + ec;
                    stg[n * 129 + m] = acc[mi][nj][0];
                    stg[(n + 1) * 129 + m] = acc[mi][nj][1];
                    stg[n * 129 + m + 8] = acc[mi][nj][2];
                    stg[(n + 1) * 129 + m + 8] = acc[mi][nj][3];
                }
            __syncthreads();
            uint32_t* dh = (uint32_t*)(isK ? g_kT_hi : g_qT_hi);
            uint32_t* dl = (uint32_t*)(isK ? g_kT_lo : g_qT_lo);
#pragma unroll
            for (int i = 0; i < 16; i++) {
                const int t = wid * 16 + i;
                const float* row = stg + t * 129;
#pragma unroll
                for (int half = 0; half < 2; half++) {
                    const float v0 = row[half * 64 + 2 * lane];
                    const float v1 = row[half * 64 + 2 * lane + 1];
                    uint32_t hi, lo;
                    split2(v0, v1, hi, lo);
                    const size_t idx =
                        ((size_t)(b * HH + h0 + half) * TT + n0 + t) * 32 + lane;
                    dh[idx] = hi;
                    dl[idx] = lo;
                }
            }
        }
    }
}

// ===========================================================================
// Tensor-core flash attention (unchanged from round 6)
// ===========================================================================
__device__ __forceinline__ void attn_load_stage(uint32_t st, int bh, int k0, int tid)
{
    const __nv_bfloat16* kh = g_kT_hi + ((size_t)bh * TT + k0) * DH;
    const __nv_bfloat16* kl = g_kT_lo + ((size_t)bh * TT + k0) * DH;
    for (int i = tid; i < 128 * 8; i += 256) {
        const int r = i >> 3, c = i & 7;
        const uint32_t d = st + (uint32_t)(r * QPITCH + c * 8) * 2;
        cp16(d, kh + (size_t)r * DH + c * 8);
        cp16(d + AQ_B, kl + (size_t)r * DH + c * 8);
    }
    const __nv_bfloat16* vh = g_v_hi + (size_t)bh * DH * TT + k0;
    const __nv_bfloat16* vl = g_v_lo + (size_t)bh * DH * TT + k0;
    for (int i = tid; i < 64 * 16; i += 256) {
        const int r = i >> 4, c = i & 15;
        const uint32_t d = st + 2 * AQ_B + (uint32_t)(r * VPITCH + c * 8) * 2;
        cp16(d, vh + (size_t)r * TT + c * 8);
        cp16(d + AV_B, vl + (size_t)r * TT + c * 8);
    }
}

__global__ void __launch_bounds__(256, 1) attn_mma()
{
    extern __shared__ char smem[];
    const uint32_t sb = smem_u32(smem);
    const uint32_t sQh = sb, sQl = sb + AQ_B;
    const uint32_t stage0 = sb + 2 * AQ_B;

    const int tid = threadIdx.x;
    const int wq = tid >> 5;
    const int lane = tid & 31;
    const int b = blockIdx.z, h = blockIdx.y;
    const int bh = b * HH + h;
    const int q0 = blockIdx.x * 128;

    {
        const __nv_bfloat16* qh = g_qT_hi + ((size_t)bh * TT + q0) * DH;
        const __nv_bfloat16* ql = g_qT_lo + ((size_t)bh * TT + q0) * DH;
        for (int i = tid; i < 128 * 8; i += 256) {
            const int r = i >> 3, c = i & 7;
            const uint32_t d = sQh + (uint32_t)(r * QPITCH + c * 8) * 2;
            cp16(d, qh + (size_t)r * DH + c * 8);
            cp16(d + AQ_B, ql + (size_t)r * DH + c * 8);
        }
        attn_load_stage(stage0, bh, 0, tid);
        cp_commit();
    }

    const int a_row = lane & 15;
    const int a_ksel = (lane >> 4) * 8;
    const int b4_row = lane & 7;
    const int b4_k = ((lane >> 3) & 1) * 8;
    const int b4_n = ((lane >> 4) & 1) * 8;

    uint32_t qfh[4][4], qfl[4][4];
    float O[8][4];
    float m0 = -__int_as_float(0x7f800000), m1 = m0;
    float l0 = 0.0f, l1 = 0.0f;
#pragma unroll
    for (int d = 0; d < 8; d++)
#pragma unroll
        for (int r = 0; r < 4; r++) O[d][r] = 0.0f;

    for (int kt = 0; kt < TT / 128; kt++) {
        const uint32_t stb = stage0 + (uint32_t)(kt & 1) * ASTAGE_B;
        if (kt + 1 < TT / 128) {
            attn_load_stage(stage0 + (uint32_t)((kt + 1) & 1) * ASTAGE_B,
                            bh, (kt + 1) * 128, tid);
            cp_commit();
            asm volatile("cp.async.wait_group 1;\n" ::: "memory");
        } else {
            asm volatile("cp.async.wait_group 0;\n" ::: "memory");
        }
        __syncthreads();

        if (kt == 0) {
#pragma unroll
            for (int ks = 0; ks < 4; ks++) {
                const uint32_t off =
                    (uint32_t)((wq * 16 + a_row) * QPITCH + ks * 16 + a_ksel) * 2;
                ldmatrix_x4(qfh[ks][0], qfh[ks][1], qfh[ks][2], qfh[ks][3], sQh + off);
                ldmatrix_x4(qfl[ks][0], qfl[ks][1], qfl[ks][2], qfl[ks][3], sQl + off);
            }
        }

        float S[16][4];
#pragma unroll
        for (int n = 0; n < 16; n++)
#pragma unroll
            for (int r = 0; r < 4; r++) S[n][r] = 0.0f;

        const uint32_t Kh = stb, Kl = stb + AQ_B;
#pragma unroll
        for (int np = 0; np < 8; np++) {
#pragma unroll
            for (int ks = 0; ks < 4; ks++) {
                const uint32_t off =
                    (uint32_t)((np * 16 + b4_n + b4_row) * QPITCH + ks * 16 + b4_k) * 2;
                uint32_t kh0, kh1, kh2, kh3, kl0, kl1, kl2, kl3;
                ldmatrix_x4(kh0, kh1, kh2, kh3, Kh + off);
                ldmatrix_x4(kl0, kl1, kl2, kl3, Kl + off);
                mma_bf16(S[2 * np], qfh[ks][0], qfh[ks][1], qfh[ks][2], qfh[ks][3], kh0, kh1);
                mma_bf16(S[2 * np], qfh[ks][0], qfh[ks][1], qfh[ks][2], qfh[ks][3], kl0, kl1);
                mma_bf16(S[2 * np], qfl[ks][0], qfl[ks][1], qfl[ks][2], qfl[ks][3], kh0, kh1);
                mma_bf16(S[2 * np + 1], qfh[ks][0], qfh[ks][1], qfh[ks][2], qfh[ks][3], kh2, kh3);
                mma_bf16(S[2 * np + 1], qfh[ks][0], qfh[ks][1], qfh[ks][2], qfh[ks][3], kl2, kl3);
                mma_bf16(S[2 * np + 1], qfl[ks][0], qfl[ks][1], qfl[ks][2], qfl[ks][3], kh2, kh3);
            }
        }

        float mx0 = -__int_as_float(0x7f800000), mx1 = mx0;
#pragma unroll
        for (int n = 0; n < 16; n++) {
            mx0 = fmaxf(mx0, fmaxf(S[n][0], S[n][1]));
            mx1 = fmaxf(mx1, fmaxf(S[n][2], S[n][3]));
        }
        mx0 = fmaxf(mx0, __shfl_xor_sync(0xffffffffu, mx0, 1));
        mx0 = fmaxf(mx0, __shfl_xor_sync(0xffffffffu, mx0, 2));
        mx1 = fmaxf(mx1, __shfl_xor_sync(0xffffffffu, mx1, 1));
        mx1 = fmaxf(mx1, __shfl_xor_sync(0xffffffffu, mx1, 2));
        const float mn0 = fmaxf(m0, mx0), mn1 = fmaxf(m1, mx1);
        const float al0 = __expf(m0 - mn0), al1 = __expf(m1 - mn1);
        float s0 = 0.0f, s1 = 0.0f;
#pragma unroll
        for (int n = 0; n < 16; n++) {
            S[n][0] = __expf(S[n][0] - mn0);
            S[n][1] = __expf(S[n][1] - mn0);
            S[n][2] = __expf(S[n][2] - mn1);
            S[n][3] = __expf(S[n][3] - mn1);
            s0 += S[n][0] + S[n][1];
            s1 += S[n][2] + S[n][3];
        }
        s0 += __shfl_xor_sync(0xffffffffu, s0, 1);
        s0 += __shfl_xor_sync(0xffffffffu, s0, 2);
        s1 += __shfl_xor_sync(0xffffffffu, s1, 1);
        s1 += __shfl_xor_sync(0xffffffffu, s1, 2);
        l0 = l0 * al0 + s0;
        l1 = l1 * al1 + s1;
        m0 = mn0;
        m1 = mn1;
#pragma unroll
        for (int d = 0; d < 8; d++) {
            O[d][0] *= al0; O[d][1] *= al0;
            O[d][2] *= al1; O[d][3] *= al1;
        }

        const uint32_t Vh = stb + 2 * AQ_B, Vl = stb + 2 * AQ_B + AV_B;
#pragma unroll
        for (int u = 0; u < 8; u++) {
            uint32_t ph[4], pl[4];
            split2(S[2 * u][0], S[2 * u][1], ph[0], pl[0]);
            split2(S[2 * u][2], S[2 * u][3], ph[1], pl[1]);
            split2(S[2 * u + 1][0], S[2 * u + 1][1], ph[2], pl[2]);
            split2(S[2 * u + 1][2], S[2 * u + 1][3], ph[3], pl[3]);
#pragma unroll
            for (int dp = 0; dp < 4; dp++) {
                const uint32_t off =
                    (uint32_t)((dp * 16 + b4_n + b4_row) * VPITCH + u * 16 + b4_k) * 2;
                uint32_t vh0, vh1, vh2, vh3, vl0, vl1, vl2, vl3;
                ldmatrix_x4(vh0, vh1, vh2, vh3, Vh + off);
                ldmatrix_x4(vl0, vl1, vl2, vl3, Vl + off);
                mma_bf16(O[2 * dp], ph[0], ph[1], ph[2], ph[3], vh0, vh1);
                mma_bf16(O[2 * dp], ph[0], ph[1], ph[2], ph[3], vl0, vl1);
                mma_bf16(O[2 * dp], pl[0], pl[1], pl[2], pl[3], vh0, vh1);
                mma_bf16(O[2 * dp + 1], ph[0], ph[1], ph[2], ph[3], vh2, vh3);
                mma_bf16(O[2 * dp + 1], ph[0], ph[1], ph[2], ph[3], vl2, vl3);
                mma_bf16(O[2 * dp + 1], pl[0], pl[1], pl[2], pl[3], vh2, vh3);
            }
        }
        __syncthreads();
    }

    const float r0 = 1.0f / l0, r1 = 1.0f / l1;
    const int row0 = q0 + wq * 16 + (lane >> 2);
    const size_t base0 = ((size_t)b * TT + row0) * CC + h * DH;
    const size_t base1 = base0 + (size_t)8 * CC;
#pragma unroll
    for (int dn = 0; dn < 8; dn++) {
        const int col = dn * 8 + 2 * (lane & 3);
        uint32_t hi, lo;
        split2(O[dn][0] * r0, O[dn][1] * r0, hi, lo);
        *(uint32_t*)&g_cT_hi[base0 + col] = hi;
        *(uint32_t*)&g_cT_lo[base0 + col] = lo;
        split2(O[dn][2] * r1, O[dn][3] * r1, hi, lo);
        *(uint32_t*)&g_cT_hi[base1 + col] = hi;
        *(uint32_t*)&g_cT_lo[base1 + col] = lo;
    }
}

// ===========================================================================
// LayerNorm
// ===========================================================================
__global__ void __launch_bounds__(256) ln_kernel(
    const float* __restrict__ gamma, const float* __restrict__ beta,
    float* __restrict__ out)
{
    const int tx = threadIdx.x, ty = threadIdx.y;
    const int b = blockIdx.y;
    const int t = blockIdx.x * 16 + tx;
    const float* yb = g_y + (long)b * CC * TT;

    float s = 0.0f, s2 = 0.0f;
    for (int c = ty; c < CC; c += 16) {
        const float v = yb[(long)c * TT + t];
        s += v;
        s2 += v * v;
    }
    __shared__ float rs[16][16], rq[16][16], mu_s[16], rstd_s[16];
    rs[ty][tx] = s;
    rq[ty][tx] = s2;
    __syncthreads();
    if (ty == 0) {
        float S = 0.0f, S2 = 0.0f;
#pragma unroll
        for (int k = 0; k < 16; k++) { S += rs[k][tx]; S2 += rq[k][tx]; }
        const float mu = S * (1.0f / CC);
        const float var = S2 * (1.0f / CC) - mu * mu;
        mu_s[tx] = mu;
        rstd_s[tx] = rsqrtf(var + LN_EPS);
    }
    __syncthreads();
    const float mu = mu_s[tx], rstd = rstd_s[tx];
    float* ob = out + (long)b * CC * TT;
    for (int c = ty; c < CC; c += 16) {
        const float v = yb[(long)c * TT + t];
        ob[(long)c * TT + t] = (v - mu) * rstd * gamma[c] + beta[c];
    }
}

// ===========================================================================
extern "C" void kernel_launch(void* const* d_in, const int* in_sizes, int n_in,
                              void* d_out, int out_size)
{
    const float* x     = (const float*)d_in[0];
    const float* wqkv  = (const float*)d_in[1];
    const float* wfc   = (const float*)d_in[2];
    const float* gamma = (const float*)d_in[3];
    const float* beta  = (const float*)d_in[4];
    float* out = (float*)d_out;

    float* y;
    cudaGetSymbolAddress((void**)&y, g_y);
    __nv_bfloat16 *wqh, *wql, *wfh, *wfl, *xth, *xtl, *cth, *ctl;
    cudaGetSymbolAddress((void**)&wqh, g_wqkv_hi);
    cudaGetSymbolAddress((void**)&wql, g_wqkv_lo);
    cudaGetSymbolAddress((void**)&wfh, g_wfc_hi);
    cudaGetSymbolAddress((void**)&wfl, g_wfc_lo);
    cudaGetSymbolAddress((void**)&xth, g_xT_hi);
    cudaGetSymbolAddress((void**)&xtl, g_xT_lo);
    cudaGetSymbolAddress((void**)&cth, g_cT_hi);
    cudaGetSymbolAddress((void**)&ctl, g_cT_lo);

    cudaFuncSetAttribute(hgemm<1>, cudaFuncAttributeMaxDynamicSharedMemorySize, GEMM_SMEM);
    cudaFuncSetAttribute(hgemm<2>, cudaFuncAttributeMaxDynamicSharedMemorySize, GEMM_SMEM);
    cudaFuncSetAttribute(attn_mma, cudaFuncAttributeMaxDynamicSharedMemorySize, ATTN_SMEM);

    // 0) precision-split conversions
    split_kernel<<<(3 * CC * CC + 255) / 256, 256>>>(wqkv, wqh, wql, 3 * CC * CC);
    split_kernel<<<(CC * CC + 255) / 256, 256>>>(wfc, wfh, wfl, CC * CC);
    tsplit_kernel<<<dim3(TT / 32, CC / 32, BB), dim3(32, 8)>>>(x, xth, xtl);

    // 1) QKV GEMM with fused attention-layout split epilogue
    hgemm<2><<<dim3(TT / GM_NT, 3 * CC / GM_MT, BB), 256, GEMM_SMEM>>>(
        wqh, wql, xth, xtl, nullptr, nullptr, 0);

    // 2) tensor-core flash attention -> g_cT hi/lo
    attn_mma<<<dim3(TT / 128, HH, BB), 256, ATTN_SMEM>>>();

    // 3) y = w_fc @ ctx + x (fused residual)
    hgemm<1><<<dim3(TT / GM_NT, CC / GM_MT, BB), 256, GEMM_SMEM>>>(
        wfh, wfl, cth, ctl, x, y, (long)CC * TT);

    // 4) LayerNorm -> out
    ln_kernel<<<dim3(TT / 16, BB), dim3(16, 16)>>>(gamma, beta, out);
}

// round 8
// speedup vs baseline: 1.0538x; 1.0538x over previous
#include <cuda_runtime.h>
#include <cuda_bf16.h>
#include <cstdint>

#define BB 2
#define CC 1024
#define TT 2048
#define HH 16
#define DH 64
#define LN_EPS 1e-6f

// ---- dense GEMM tiling (round-6 optimum: KC=32, 2-stage, 2 CTAs/SM) ----
#define GM_MT 128
#define GM_NT 128
#define GM_KC 32
#define NCHUNK (CC / GM_KC)            // 32
#define PITCH 40
#define A_BYTES (GM_MT * PITCH * 2)
#define B_BYTES (GM_NT * PITCH * 2)
#define STAGE_BYTES (2 * A_BYTES + 2 * B_BYTES)  // 40960
#define GEMM_SMEM (2 * STAGE_BYTES)              // 81920

// ---- attention tiling: kt-tile 64 -> 108KB smem -> 2 CTAs/SM ----
#define QPITCH 72
#define KT 64
#define AQ_B (128 * QPITCH * 2)         // 18432 (Q hi or lo)
#define AK_B (KT * QPITCH * 2)          // 9216 (one K or V buffer)
#define ASTAGE_B (4 * AK_B)             // 36864 (K hi/lo + V hi/lo)
#define ATTN_SMEM (2 * AQ_B + 2 * ASTAGE_B)      // 110592

// ---- scratch ----
__device__ float g_y[(size_t)BB * CC * TT];
__device__ __nv_bfloat16 g_wqkv_hi[3 * CC * CC], g_wqkv_lo[3 * CC * CC];
__device__ __nv_bfloat16 g_wfc_hi[CC * CC], g_wfc_lo[CC * CC];
__device__ __nv_bfloat16 g_xT_hi[(size_t)BB * TT * CC], g_xT_lo[(size_t)BB * TT * CC];
__device__ __nv_bfloat16 g_cT_hi[(size_t)BB * TT * CC], g_cT_lo[(size_t)BB * TT * CC];
__device__ __nv_bfloat16 g_qT_hi[(size_t)BB * HH * TT * DH], g_qT_lo[(size_t)BB * HH * TT * DH];
__device__ __nv_bfloat16 g_kT_hi[(size_t)BB * HH * TT * DH], g_kT_lo[(size_t)BB * HH * TT * DH];
__device__ __nv_bfloat16 g_v_hi[(size_t)BB * HH * DH * TT], g_v_lo[(size_t)BB * HH * DH * TT];

// ===========================================================================
__device__ __forceinline__ uint32_t smem_u32(const void* p) {
    return (uint32_t)__cvta_generic_to_shared(p);
}
__device__ __forceinline__ void cp16(uint32_t dst, const void* src) {
    asm volatile("cp.async.cg.shared.global [%0], [%1], 16;\n" :: "r"(dst), "l"(src));
}
__device__ __forceinline__ void cp_commit() {
    asm volatile("cp.async.commit_group;\n" ::: "memory");
}
__device__ __forceinline__ void ldmatrix_x4(uint32_t& a0, uint32_t& a1, uint32_t& a2,
                                            uint32_t& a3, uint32_t addr) {
    asm volatile("ldmatrix.sync.aligned.m8n8.x4.shared.b16 {%0,%1,%2,%3}, [%4];"
                 : "=r"(a0), "=r"(a1), "=r"(a2), "=r"(a3) : "r"(addr));
}
__device__ __forceinline__ void mma_bf16(float* c,
                                         uint32_t a0, uint32_t a1, uint32_t a2, uint32_t a3,
                                         uint32_t b0, uint32_t b1) {
    asm volatile(
        "mma.sync.aligned.m16n8k16.row.col.f32.bf16.bf16.f32 "
        "{%0,%1,%2,%3}, {%4,%5,%6,%7}, {%8,%9}, {%0,%1,%2,%3};"
        : "+f"(c[0]), "+f"(c[1]), "+f"(c[2]), "+f"(c[3])
        : "r"(a0), "r"(a1), "r"(a2), "r"(a3), "r"(b0), "r"(b1));
}
__device__ __forceinline__ uint32_t cvt2(float f0, float f1) {
    uint32_t r;
    asm("cvt.rn.bf16x2.f32 %0, %1, %2;" : "=r"(r) : "f"(f1), "f"(f0));
    return r;
}
__device__ __forceinline__ void split2(float f0, float f1, uint32_t& hi, uint32_t& lo) {
    hi = cvt2(f0, f1);
    const float h0 = __uint_as_float(hi << 16);
    const float h1 = __uint_as_float(hi & 0xffff0000u);
    lo = cvt2(f0 - h0, f1 - h1);
}

// ===========================================================================
// conversions
// ===========================================================================
__global__ void __launch_bounds__(256) split_kernel(
    const float* __restrict__ in, __nv_bfloat16* __restrict__ hi,
    __nv_bfloat16* __restrict__ lo, int n)
{
    int i = blockIdx.x * 256 + threadIdx.x;
    if (i < n) {
        const float v = in[i];
        const __nv_bfloat16 h = __float2bfloat16(v);
        hi[i] = h;
        lo[i] = __float2bfloat16(v - __bfloat162float(h));
    }
}

__global__ void __launch_bounds__(256) tsplit_kernel(
    const float* __restrict__ in, __nv_bfloat16* __restrict__ hi,
    __nv_bfloat16* __restrict__ lo)
{
    __shared__ float tile[32][33];
    const int b = blockIdx.z;
    const int t0 = blockIdx.x * 32, c0 = blockIdx.y * 32;
    const float* ib = in + (size_t)b * CC * TT;
    for (int j = threadIdx.y; j < 32; j += 8)
        tile[j][threadIdx.x] = ib[(size_t)(c0 + j) * TT + t0 + threadIdx.x];
    __syncthreads();
    __nv_bfloat16* hb = hi + (size_t)b * TT * CC;
    __nv_bfloat16* lb = lo + (size_t)b * TT * CC;
    for (int j = threadIdx.y; j < 32; j += 8) {
        const float v = tile[threadIdx.x][j];
        const __nv_bfloat16 h = __float2bfloat16(v);
        const size_t o = (size_t)(t0 + j) * CC + c0 + threadIdx.x;
        hb[o] = h;
        lb[o] = __float2bfloat16(v - __bfloat162float(h));
    }
}

// ===========================================================================
// mma.sync bf16-split GEMM (round-6 config); EPI 1 = residual, 2 = QKV split
// ===========================================================================
__device__ __forceinline__ void g_load_stage(
    uint32_t st, int kc,
    const __nv_bfloat16* __restrict__ Ahi, const __nv_bfloat16* __restrict__ Alo,
    const __nv_bfloat16* __restrict__ Bhi, const __nv_bfloat16* __restrict__ Blo,
    int m0, int n0, int tid)
{
    for (int i = tid; i < GM_MT * 4; i += 256) {
        const int r = i >> 2, c = i & 3;
        const uint32_t dst = st + (uint32_t)(r * PITCH + c * 8) * 2;
        const size_t g = (size_t)(m0 + r) * CC + kc + c * 8;
        cp16(dst, Ahi + g);
        cp16(dst + A_BYTES, Alo + g);
    }
    for (int i = tid; i < GM_NT * 4; i += 256) {
        const int r = i >> 2, c = i & 3;
        const uint32_t dst = st + 2 * A_BYTES + (uint32_t)(r * PITCH + c * 8) * 2;
        const size_t g = (size_t)(n0 + r) * CC + kc + c * 8;
        cp16(dst, Bhi + g);
        cp16(dst + B_BYTES, Blo + g);
    }
    cp_commit();
}

template <int EPI>
__global__ void __launch_bounds__(256) hgemm(
    const __nv_bfloat16* __restrict__ Ahi, const __nv_bfloat16* __restrict__ Alo,
    const __nv_bfloat16* __restrict__ BhiAll, const __nv_bfloat16* __restrict__ BloAll,
    const float* __restrict__ Res, float* __restrict__ Cout, long outBatchStride)
{
    extern __shared__ char smem[];
    const uint32_t sbase = smem_u32(smem);

    const int tid = threadIdx.x;
    const int wid = tid >> 5;
    const int lane = tid & 31;
    const int b = blockIdx.z;
    const int m0 = blockIdx.y * GM_MT;
    const int n0 = blockIdx.x * GM_NT;
    const int wm = (wid >> 2) * 64;
    const int wn = (wid & 3) * 32;

    const __nv_bfloat16* Bhi = BhiAll + (size_t)b * TT * CC;
    const __nv_bfloat16* Blo = BloAll + (size_t)b * TT * CC;

    float acc[4][4][4];
#pragma unroll
    for (int i = 0; i < 4; i++)
#pragma unroll
        for (int j = 0; j < 4; j++)
#pragma unroll
            for (int r = 0; r < 4; r++) acc[i][j][r] = 0.0f;

    const int a_row = lane & 15;
    const int a_ksel = (lane >> 4) * 8;
    const int b4_row = lane & 7;
    const int b4_k = ((lane >> 3) & 1) * 8;
    const int b4_n = ((lane >> 4) & 1) * 8;

    g_load_stage(sbase, 0, Ahi, Alo, Bhi, Blo, m0, n0, tid);

    for (int c = 0; c < NCHUNK; c++) {
        const uint32_t st = sbase + (uint32_t)(c & 1) * STAGE_BYTES;
        if (c + 1 < NCHUNK) {
            g_load_stage(sbase + (uint32_t)((c + 1) & 1) * STAGE_BYTES,
                         (c + 1) * GM_KC, Ahi, Alo, Bhi, Blo, m0, n0, tid);
            asm volatile("cp.async.wait_group 1;\n" ::: "memory");
        } else {
            asm volatile("cp.async.wait_group 0;\n" ::: "memory");
        }
        __syncthreads();

        const uint32_t sAh = st;
        const uint32_t sAl = st + A_BYTES;
        const uint32_t sBh = st + 2 * A_BYTES;
        const uint32_t sBl = st + 2 * A_BYTES + B_BYTES;

#pragma unroll
        for (int kk = 0; kk < GM_KC; kk += 16) {
            uint32_t ah[4][4], al[4][4], bh[4][2], bl[4][2];
#pragma unroll
            for (int mi = 0; mi < 4; mi++) {
                const uint32_t off =
                    (uint32_t)((wm + mi * 16 + a_row) * PITCH + kk + a_ksel) * 2;
                ldmatrix_x4(ah[mi][0], ah[mi][1], ah[mi][2], ah[mi][3], sAh + off);
                ldmatrix_x4(al[mi][0], al[mi][1], al[mi][2], al[mi][3], sAl + off);
            }
#pragma unroll
            for (int p = 0; p < 2; p++) {
                const uint32_t off =
                    (uint32_t)((wn + p * 16 + b4_n + b4_row) * PITCH + kk + b4_k) * 2;
                ldmatrix_x4(bh[2 * p][0], bh[2 * p][1], bh[2 * p + 1][0],
                            bh[2 * p + 1][1], sBh + off);
                ldmatrix_x4(bl[2 * p][0], bl[2 * p][1], bl[2 * p + 1][0],
                            bl[2 * p + 1][1], sBl + off);
            }
#pragma unroll
            for (int mi = 0; mi < 4; mi++)
#pragma unroll
                for (int nj = 0; nj < 4; nj++) {
                    float* a = acc[mi][nj];
                    mma_bf16(a, ah[mi][0], ah[mi][1], ah[mi][2], ah[mi][3],
                             bh[nj][0], bh[nj][1]);
                    mma_bf16(a, ah[mi][0], ah[mi][1], ah[mi][2], ah[mi][3],
                             bl[nj][0], bl[nj][1]);
                    mma_bf16(a, al[mi][0], al[mi][1], al[mi][2], al[mi][3],
                             bh[nj][0], bh[nj][1]);
                }
        }
        __syncthreads();
    }

    const int er = lane >> 2;
    const int ec = (lane & 3) * 2;

    if (EPI == 1) {
        float* Cb = Cout + (size_t)b * outBatchStride;
        const float* Rb = Res + (size_t)b * CC * TT;
#pragma unroll
        for (int mi = 0; mi < 4; mi++)
#pragma unroll
            for (int nj = 0; nj < 4; nj++) {
                const int m = m0 + wm + mi * 16 + er;
                const int n = n0 + wn + nj * 8 + ec;
                float2 v0 = make_float2(acc[mi][nj][0], acc[mi][nj][1]);
                float2 v1 = make_float2(acc[mi][nj][2], acc[mi][nj][3]);
                const float2 r0 = *(const float2*)(Rb + (size_t)m * TT + n);
                const float2 r1 = *(const float2*)(Rb + (size_t)(m + 8) * TT + n);
                v0.x += r0.x; v0.y += r0.y;
                v1.x += r1.x; v1.y += r1.y;
                *(float2*)(Cb + (size_t)m * TT + n) = v0;
                *(float2*)(Cb + (size_t)(m + 8) * TT + n) = v1;
            }
    } else {
        if (m0 >= 2 * CC) {
            const int chBase = m0 - 2 * CC;
            uint32_t* vhi = (uint32_t*)g_v_hi;
            uint32_t* vlo = (uint32_t*)g_v_lo;
#pragma unroll
            for (int mi = 0; mi < 4; mi++)
#pragma unroll
                for (int nj = 0; nj < 4; nj++) {
                    const int n = n0 + wn + nj * 8 + ec;
#pragma unroll
                    for (int rr = 0; rr < 2; rr++) {
                        const int ch = chBase + wm + mi * 16 + er + rr * 8;
                        const int bh = b * HH + (ch >> 6);
                        const int d = ch & 63;
                        uint32_t hi, lo;
                        split2(acc[mi][nj][2 * rr], acc[mi][nj][2 * rr + 1], hi, lo);
                        const size_t idx = (((size_t)bh * DH + d) * TT + n) >> 1;
                        vhi[idx] = hi;
                        vlo[idx] = lo;
                    }
                }
        } else {
            const bool isK = (m0 >= CC);
            const int chBase = isK ? (m0 - CC) : m0;
            const int h0 = chBase >> 6;
            float* stg = (float*)smem;  // [n(128)][m(128)] pitch 129
#pragma unroll
            for (int mi = 0; mi < 4; mi++)
#pragma unroll
                for (int nj = 0; nj < 4; nj++) {
                    const int m = wm + mi * 16 + er;
                    const int n = wn + nj * 8 + ec;
                    stg[n * 129 + m] = acc[mi][nj][0];
                    stg[(n + 1) * 129 + m] = acc[mi][nj][1];
                    stg[n * 129 + m + 8] = acc[mi][nj][2];
                    stg[(n + 1) * 129 + m + 8] = acc[mi][nj][3];
                }
            __syncthreads();
            uint32_t* dh = (uint32_t*)(isK ? g_kT_hi : g_qT_hi);
            uint32_t* dl = (uint32_t*)(isK ? g_kT_lo : g_qT_lo);
#pragma unroll
            for (int i = 0; i < 16; i++) {
                const int t = wid * 16 + i;
                const float* row = stg + t * 129;
#pragma unroll
                for (int half = 0; half < 2; half++) {
                    const float v0 = row[half * 64 + 2 * lane];
                    const float v1 = row[half * 64 + 2 * lane + 1];
                    uint32_t hi, lo;
                    split2(v0, v1, hi, lo);
                    const size_t idx =
                        ((size_t)(b * HH + h0 + half) * TT + n0 + t) * 32 + lane;
                    dh[idx] = hi;
                    dl[idx] = lo;
                }
            }
        }
    }
}

// ===========================================================================
// Tensor-core flash attention: kt-tile 64, 108KB smem -> 2 CTAs/SM
// ===========================================================================
__device__ __forceinline__ void attn_load_stage(uint32_t st, int bh, int k0, int tid)
{
    // K: KT rows x 64 d (hi/lo)
    const __nv_bfloat16* kh = g_kT_hi + ((size_t)bh * TT + k0) * DH;
    const __nv_bfloat16* kl = g_kT_lo + ((size_t)bh * TT + k0) * DH;
    for (int i = tid; i < KT * 8; i += 256) {
        const int r = i >> 3, c = i & 7;
        const uint32_t d = st + (uint32_t)(r * QPITCH + c * 8) * 2;
        cp16(d, kh + (size_t)r * DH + c * 8);
        cp16(d + AK_B, kl + (size_t)r * DH + c * 8);
    }
    // V: 64 d-rows x KT t (hi/lo)
    const __nv_bfloat16* vh = g_v_hi + (size_t)bh * DH * TT + k0;
    const __nv_bfloat16* vl = g_v_lo + (size_t)bh * DH * TT + k0;
    for (int i = tid; i < 64 * (KT / 8); i += 256) {
        const int r = i >> 3, c = i & 7;
        const uint32_t d = st + 2 * AK_B + (uint32_t)(r * QPITCH + c * 8) * 2;
        cp16(d, vh + (size_t)r * TT + c * 8);
        cp16(d + AK_B, vl + (size_t)r * TT + c * 8);
    }
}

__global__ void __launch_bounds__(256, 2) attn_mma()
{
    extern __shared__ char smem[];
    const uint32_t sb = smem_u32(smem);
    const uint32_t sQh = sb, sQl = sb + AQ_B;
    const uint32_t stage0 = sb + 2 * AQ_B;

    const int tid = threadIdx.x;
    const int wq = tid >> 5;
    const int lane = tid & 31;
    const int b = blockIdx.z, h = blockIdx.y;
    const int bh = b * HH + h;
    const int q0 = blockIdx.x * 128;

    {
        const __nv_bfloat16* qh = g_qT_hi + ((size_t)bh * TT + q0) * DH;
        const __nv_bfloat16* ql = g_qT_lo + ((size_t)bh * TT + q0) * DH;
        for (int i = tid; i < 128 * 8; i += 256) {
            const int r = i >> 3, c = i & 7;
            const uint32_t d = sQh + (uint32_t)(r * QPITCH + c * 8) * 2;
            cp16(d, qh + (size_t)r * DH + c * 8);
            cp16(d + AQ_B, ql + (size_t)r * DH + c * 8);
        }
        attn_load_stage(stage0, bh, 0, tid);
        cp_commit();
    }

    const int a_row = lane & 15;
    const int a_ksel = (lane >> 4) * 8;
    const int b4_row = lane & 7;
    const int b4_k = ((lane >> 3) & 1) * 8;
    const int b4_n = ((lane >> 4) & 1) * 8;

    uint32_t qfh[4][4], qfl[4][4];
    float O[8][4];
    float m0 = -__int_as_float(0x7f800000), m1 = m0;
    float l0 = 0.0f, l1 = 0.0f;
#pragma unroll
    for (int d = 0; d < 8; d++)
#pragma unroll
        for (int r = 0; r < 4; r++) O[d][r] = 0.0f;

    for (int kt = 0; kt < TT / KT; kt++) {
        const uint32_t stb = stage0 + (uint32_t)(kt & 1) * ASTAGE_B;
        if (kt + 1 < TT / KT) {
            attn_load_stage(stage0 + (uint32_t)((kt + 1) & 1) * ASTAGE_B,
                            bh, (kt + 1) * KT, tid);
            cp_commit();
            asm volatile("cp.async.wait_group 1;\n" ::: "memory");
        } else {
            asm volatile("cp.async.wait_group 0;\n" ::: "memory");
        }
        __syncthreads();

        if (kt == 0) {
#pragma unroll
            for (int ks = 0; ks < 4; ks++) {
                const uint32_t off =
                    (uint32_t)((wq * 16 + a_row) * QPITCH + ks * 16 + a_ksel) * 2;
                ldmatrix_x4(qfh[ks][0], qfh[ks][1], qfh[ks][2], qfh[ks][3], sQh + off);
                ldmatrix_x4(qfl[ks][0], qfl[ks][1], qfl[ks][2], qfl[ks][3], sQl + off);
            }
        }

        float S[8][4];
#pragma unroll
        for (int n = 0; n < 8; n++)
#pragma unroll
            for (int r = 0; r < 4; r++) S[n][r] = 0.0f;

        const uint32_t Kh = stb, Kl = stb + AK_B;
#pragma unroll
        for (int np = 0; np < 4; np++) {
#pragma unroll
            for (int ks = 0; ks < 4; ks++) {
                const uint32_t off =
                    (uint32_t)((np * 16 + b4_n + b4_row) * QPITCH + ks * 16 + b4_k) * 2;
                uint32_t kh0, kh1, kh2, kh3, kl0, kl1, kl2, kl3;
                ldmatrix_x4(kh0, kh1, kh2, kh3, Kh + off);
                ldmatrix_x4(kl0, kl1, kl2, kl3, Kl + off);
                mma_bf16(S[2 * np], qfh[ks][0], qfh[ks][1], qfh[ks][2], qfh[ks][3], kh0, kh1);
                mma_bf16(S[2 * np], qfh[ks][0], qfh[ks][1], qfh[ks][2], qfh[ks][3], kl0, kl1);
                mma_bf16(S[2 * np], qfl[ks][0], qfl[ks][1], qfl[ks][2], qfl[ks][3], kh0, kh1);
                mma_bf16(S[2 * np + 1], qfh[ks][0], qfh[ks][1], qfh[ks][2], qfh[ks][3], kh2, kh3);
                mma_bf16(S[2 * np + 1], qfh[ks][0], qfh[ks][1], qfh[ks][2], qfh[ks][3], kl2, kl3);
                mma_bf16(S[2 * np + 1], qfl[ks][0], qfl[ks][1], qfl[ks][2], qfl[ks][3], kh2, kh3);
            }
        }

        // online softmax (rows lane/4 and +8)
        float mx0 = -__int_as_float(0x7f800000), mx1 = mx0;
#pragma unroll
        for (int n = 0; n < 8; n++) {
            mx0 = fmaxf(mx0, fmaxf(S[n][0], S[n][1]));
            mx1 = fmaxf(mx1, fmaxf(S[n][2], S[n][3]));
        }
        mx0 = fmaxf(mx0, __shfl_xor_sync(0xffffffffu, mx0, 1));
        mx0 = fmaxf(mx0, __shfl_xor_sync(0xffffffffu, mx0, 2));
        mx1 = fmaxf(mx1, __shfl_xor_sync(0xffffffffu, mx1, 1));
        mx1 = fmaxf(mx1, __shfl_xor_sync(0xffffffffu, mx1, 2));
        const float mn0 = fmaxf(m0, mx0), mn1 = fmaxf(m1, mx1);
        const float al0 = __expf(m0 - mn0), al1 = __expf(m1 - mn1);
        float s0 = 0.0f, s1 = 0.0f;
#pragma unroll
        for (int n = 0; n < 8; n++) {
            S[n][0] = __expf(S[n][0] - mn0);
            S[n][1] = __expf(S[n][1] - mn0);
            S[n][2] = __expf(S[n][2] - mn1);
            S[n][3] = __expf(S[n][3] - mn1);
            s0 += S[n][0] + S[n][1];
            s1 += S[n][2] + S[n][3];
        }
        s0 += __shfl_xor_sync(0xffffffffu, s0, 1);
        s0 += __shfl_xor_sync(0xffffffffu, s0, 2);
        s1 += __shfl_xor_sync(0xffffffffu, s1, 1);
        s1 += __shfl_xor_sync(0xffffffffu, s1, 2);
        l0 = l0 * al0 + s0;
        l1 = l1 * al1 + s1;
        m0 = mn0;
        m1 = mn1;
#pragma unroll
        for (int d = 0; d < 8; d++) {
            O[d][0] *= al0; O[d][1] *= al0;
            O[d][2] *= al1; O[d][3] *= al1;
        }

        // O += P V
        const uint32_t Vh = stb + 2 * AK_B, Vl = stb + 3 * AK_B;
#pragma unroll
        for (int u = 0; u < 4; u++) {
            uint32_t ph[4], pl[4];
            split2(S[2 * u][0], S[2 * u][1], ph[0], pl[0]);
            split2(S[2 * u][2], S[2 * u][3], ph[1], pl[1]);
            split2(S[2 * u + 1][0], S[2 * u + 1][1], ph[2], pl[2]);
            split2(S[2 * u + 1][2], S[2 * u + 1][3], ph[3], pl[3]);
#pragma unroll
            for (int dp = 0; dp < 4; dp++) {
                const uint32_t off =
                    (uint32_t)((dp * 16 + b4_n + b4_row) * QPITCH + u * 16 + b4_k) * 2;
                uint32_t vh0, vh1, vh2, vh3, vl0, vl1, vl2, vl3;
                ldmatrix_x4(vh0, vh1, vh2, vh3, Vh + off);
                ldmatrix_x4(vl0, vl1, vl2, vl3, Vl + off);
                mma_bf16(O[2 * dp], ph[0], ph[1], ph[2], ph[3], vh0, vh1);
                mma_bf16(O[2 * dp], ph[0], ph[1], ph[2], ph[3], vl0, vl1);
                mma_bf16(O[2 * dp], pl[0], pl[1], pl[2], pl[3], vh0, vh1);
                mma_bf16(O[2 * dp + 1], ph[0], ph[1], ph[2], ph[3], vh2, vh3);
                mma_bf16(O[2 * dp + 1], ph[0], ph[1], ph[2], ph[3], vl2, vl3);
                mma_bf16(O[2 * dp + 1], pl[0], pl[1], pl[2], pl[3], vh2, vh3);
            }
        }
        __syncthreads();
    }

    const float r0 = 1.0f / l0, r1 = 1.0f / l1;
    const int row0 = q0 + wq * 16 + (lane >> 2);
    const size_t base0 = ((size_t)b * TT + row0) * CC + h * DH;
    const size_t base1 = base0 + (size_t)8 * CC;
#pragma unroll
    for (int dn = 0; dn < 8; dn++) {
        const int col = dn * 8 + 2 * (lane & 3);
        uint32_t hi, lo;
        split2(O[dn][0] * r0, O[dn][1] * r0, hi, lo);
        *(uint32_t*)&g_cT_hi[base0 + col] = hi;
        *(uint32_t*)&g_cT_lo[base0 + col] = lo;
        split2(O[dn][2] * r1, O[dn][3] * r1, hi, lo);
        *(uint32_t*)&g_cT_hi[base1 + col] = hi;
        *(uint32_t*)&g_cT_lo[base1 + col] = lo;
    }
}

// ===========================================================================
// LayerNorm
// ===========================================================================
__global__ void __launch_bounds__(256) ln_kernel(
    const float* __restrict__ gamma, const float* __restrict__ beta,
    float* __restrict__ out)
{
    const int tx = threadIdx.x, ty = threadIdx.y;
    const int b = blockIdx.y;
    const int t = blockIdx.x * 16 + tx;
    const float* yb = g_y + (long)b * CC * TT;

    float s = 0.0f, s2 = 0.0f;
    for (int c = ty; c < CC; c += 16) {
        const float v = yb[(long)c * TT + t];
        s += v;
        s2 += v * v;
    }
    __shared__ float rs[16][16], rq[16][16], mu_s[16], rstd_s[16];
    rs[ty][tx] = s;
    rq[ty][tx] = s2;
    __syncthreads();
    if (ty == 0) {
        float S = 0.0f, S2 = 0.0f;
#pragma unroll
        for (int k = 0; k < 16; k++) { S += rs[k][tx]; S2 += rq[k][tx]; }
        const float mu = S * (1.0f / CC);
        const float var = S2 * (1.0f / CC) - mu * mu;
        mu_s[tx] = mu;
        rstd_s[tx] = rsqrtf(var + LN_EPS);
    }
    __syncthreads();
    const float mu = mu_s[tx], rstd = rstd_s[tx];
    float* ob = out + (long)b * CC * TT;
    for (int c = ty; c < CC; c += 16) {
        const float v = yb[(long)c * TT + t];
        ob[(long)c * TT + t] = (v - mu) * rstd * gamma[c] + beta[c];
    }
}

// ===========================================================================
extern "C" void kernel_launch(void* const* d_in, const int* in_sizes, int n_in,
                              void* d_out, int out_size)
{
    const float* x     = (const float*)d_in[0];
    const float* wqkv  = (const float*)d_in[1];
    const float* wfc   = (const float*)d_in[2];
    const float* gamma = (const float*)d_in[3];
    const float* beta  = (const float*)d_in[4];
    float* out = (float*)d_out;

    float* y;
    cudaGetSymbolAddress((void**)&y, g_y);
    __nv_bfloat16 *wqh, *wql, *wfh, *wfl, *xth, *xtl, *cth, *ctl;
    cudaGetSymbolAddress((void**)&wqh, g_wqkv_hi);
    cudaGetSymbolAddress((void**)&wql, g_wqkv_lo);
    cudaGetSymbolAddress((void**)&wfh, g_wfc_hi);
    cudaGetSymbolAddress((void**)&wfl, g_wfc_lo);
    cudaGetSymbolAddress((void**)&xth, g_xT_hi);
    cudaGetSymbolAddress((void**)&xtl, g_xT_lo);
    cudaGetSymbolAddress((void**)&cth, g_cT_hi);
    cudaGetSymbolAddress((void**)&ctl, g_cT_lo);

    cudaFuncSetAttribute(hgemm<1>, cudaFuncAttributeMaxDynamicSharedMemorySize, GEMM_SMEM);
    cudaFuncSetAttribute(hgemm<2>, cudaFuncAttributeMaxDynamicSharedMemorySize, GEMM_SMEM);
    cudaFuncSetAttribute(attn_mma, cudaFuncAttributeMaxDynamicSharedMemorySize, ATTN_SMEM);

    // 0) precision-split conversions
    split_kernel<<<(3 * CC * CC + 255) / 256, 256>>>(wqkv, wqh, wql, 3 * CC * CC);
    split_kernel<<<(CC * CC + 255) / 256, 256>>>(wfc, wfh, wfl, CC * CC);
    tsplit_kernel<<<dim3(TT / 32, CC / 32, BB), dim3(32, 8)>>>(x, xth, xtl);

    // 1) QKV GEMM with fused attention-layout split epilogue
    hgemm<2><<<dim3(TT / GM_NT, 3 * CC / GM_MT, BB), 256, GEMM_SMEM>>>(
        wqh, wql, xth, xtl, nullptr, nullptr, 0);

    // 2) tensor-core flash attention (2 CTAs/SM) -> g_cT hi/lo
    attn_mma<<<dim3(TT / 128, HH, BB), 256, ATTN_SMEM>>>();

    // 3) y = w_fc @ ctx + x (fused residual)
    hgemm<1><<<dim3(TT / GM_NT, CC / GM_MT, BB), 256, GEMM_SMEM>>>(
        wfh, wfl, cth, ctl, x, y, (long)CC * TT);

    // 4) LayerNorm -> out
    ln_kernel<<<dim3(TT / 16, BB), dim3(16, 16)>>>(gamma, beta, out);
}

// round 9
// speedup vs baseline: 1.1556x; 1.0965x over previous
#include <cuda_runtime.h>
#include <cuda_bf16.h>
#include <cuda_fp16.h>
#include <cstdint>

#define BB 2
#define CC 1024
#define TT 2048
#define HH 16
#define DH 64
#define LN_EPS 1e-6f

// ---- dense GEMM tiling (KC=32, 2-stage, 2 CTAs/SM) ----
#define GM_MT 128
#define GM_NT 128
#define GM_KC 32
#define NCHUNK (CC / GM_KC)            // 32
#define PITCH 40
#define A_BYTES (GM_MT * PITCH * 2)     // 10240
#define B_BYTES (GM_NT * PITCH * 2)     // 10240
// MODE 0 (bf16 3-term): stage = A hi/lo + B hi/lo
#define STAGE0_BYTES (2 * A_BYTES + 2 * B_BYTES)  // 40960
#define GEMM_SMEM0 (2 * STAGE0_BYTES)             // 81920
// MODE 1 (fp16 asym 2-term): stage = A single + B hi/lo
#define STAGE1_BYTES (A_BYTES + 2 * B_BYTES)      // 30720
#define GEMM_SMEM1 (2 * STAGE1_BYTES)             // 61440

// ---- attention tiling: kt-tile 64, 108KB smem, 2 CTAs/SM ----
#define QPITCH 72
#define KT 64
#define AQ_B (128 * QPITCH * 2)
#define AK_B (KT * QPITCH * 2)
#define ASTAGE_B (4 * AK_B)
#define ATTN_SMEM (2 * AQ_B + 2 * ASTAGE_B)      // 110592

// ---- scratch ----
__device__ float g_y[(size_t)BB * CC * TT];
__device__ __nv_bfloat16 g_wqkv_hi[3 * CC * CC], g_wqkv_lo[3 * CC * CC];
__device__ __half g_wfc_h[CC * CC];
__device__ __nv_bfloat16 g_xT_hi[(size_t)BB * TT * CC], g_xT_lo[(size_t)BB * TT * CC];
__device__ __half g_cT_hi[(size_t)BB * TT * CC], g_cT_lo[(size_t)BB * TT * CC];
__device__ __nv_bfloat16 g_qT_hi[(size_t)BB * HH * TT * DH], g_qT_lo[(size_t)BB * HH * TT * DH];
__device__ __nv_bfloat16 g_kT_hi[(size_t)BB * HH * TT * DH], g_kT_lo[(size_t)BB * HH * TT * DH];
__device__ __half g_v_hi[(size_t)BB * HH * DH * TT], g_v_lo[(size_t)BB * HH * DH * TT];

// ===========================================================================
__device__ __forceinline__ uint32_t smem_u32(const void* p) {
    return (uint32_t)__cvta_generic_to_shared(p);
}
__device__ __forceinline__ void cp16(uint32_t dst, const void* src) {
    asm volatile("cp.async.cg.shared.global [%0], [%1], 16;\n" :: "r"(dst), "l"(src));
}
__device__ __forceinline__ void cp_commit() {
    asm volatile("cp.async.commit_group;\n" ::: "memory");
}
__device__ __forceinline__ void ldmatrix_x4(uint32_t& a0, uint32_t& a1, uint32_t& a2,
                                            uint32_t& a3, uint32_t addr) {
    asm volatile("ldmatrix.sync.aligned.m8n8.x4.shared.b16 {%0,%1,%2,%3}, [%4];"
                 : "=r"(a0), "=r"(a1), "=r"(a2), "=r"(a3) : "r"(addr));
}
__device__ __forceinline__ void mma_bf16(float* c,
                                         uint32_t a0, uint32_t a1, uint32_t a2, uint32_t a3,
                                         uint32_t b0, uint32_t b1) {
    asm volatile(
        "mma.sync.aligned.m16n8k16.row.col.f32.bf16.bf16.f32 "
        "{%0,%1,%2,%3}, {%4,%5,%6,%7}, {%8,%9}, {%0,%1,%2,%3};"
        : "+f"(c[0]), "+f"(c[1]), "+f"(c[2]), "+f"(c[3])
        : "r"(a0), "r"(a1), "r"(a2), "r"(a3), "r"(b0), "r"(b1));
}
__device__ __forceinline__ void mma_f16(float* c,
                                        uint32_t a0, uint32_t a1, uint32_t a2, uint32_t a3,
                                        uint32_t b0, uint32_t b1) {
    asm volatile(
        "mma.sync.aligned.m16n8k16.row.col.f32.f16.f16.f32 "
        "{%0,%1,%2,%3}, {%4,%5,%6,%7}, {%8,%9}, {%0,%1,%2,%3};"
        : "+f"(c[0]), "+f"(c[1]), "+f"(c[2]), "+f"(c[3])
        : "r"(a0), "r"(a1), "r"(a2), "r"(a3), "r"(b0), "r"(b1));
}
__device__ __forceinline__ uint32_t cvt2(float f0, float f1) {  // bf16x2 {lo=f0,hi=f1}
    uint32_t r;
    asm("cvt.rn.bf16x2.f32 %0, %1, %2;" : "=r"(r) : "f"(f1), "f"(f0));
    return r;
}
__device__ __forceinline__ void split2(float f0, float f1, uint32_t& hi, uint32_t& lo) {
    hi = cvt2(f0, f1);
    const float h0 = __uint_as_float(hi << 16);
    const float h1 = __uint_as_float(hi & 0xffff0000u);
    lo = cvt2(f0 - h0, f1 - h1);
}
__device__ __forceinline__ uint32_t cvt2h(float f0, float f1) {  // f16x2 {lo=f0,hi=f1}
    uint32_t r;
    asm("cvt.rn.f16x2.f32 %0, %1, %2;" : "=r"(r) : "f"(f1), "f"(f0));
    return r;
}
__device__ __forceinline__ void split2h(float f0, float f1, uint32_t& hi, uint32_t& lo) {
    hi = cvt2h(f0, f1);
    const float h0 = __half2float(__ushort_as_half((unsigned short)(hi & 0xffffu)));
    const float h1 = __half2float(__ushort_as_half((unsigned short)(hi >> 16)));
    lo = cvt2h(f0 - h0, f1 - h1);
}

// ===========================================================================
// conversions
// ===========================================================================
__global__ void __launch_bounds__(256) split_kernel(
    const float* __restrict__ in, __nv_bfloat16* __restrict__ hi,
    __nv_bfloat16* __restrict__ lo, int n)
{
    int i = blockIdx.x * 256 + threadIdx.x;
    if (i < n) {
        const float v = in[i];
        const __nv_bfloat16 h = __float2bfloat16(v);
        hi[i] = h;
        lo[i] = __float2bfloat16(v - __bfloat162float(h));
    }
}

__global__ void __launch_bounds__(256) cvtf16_kernel(
    const float* __restrict__ in, __half* __restrict__ out, int n)
{
    int i = blockIdx.x * 256 + threadIdx.x;
    if (i < n) out[i] = __float2half_rn(in[i]);
}

__global__ void __launch_bounds__(256) tsplit_kernel(
    const float* __restrict__ in, __nv_bfloat16* __restrict__ hi,
    __nv_bfloat16* __restrict__ lo)
{
    __shared__ float tile[32][33];
    const int b = blockIdx.z;
    const int t0 = blockIdx.x * 32, c0 = blockIdx.y * 32;
    const float* ib = in + (size_t)b * CC * TT;
    for (int j = threadIdx.y; j < 32; j += 8)
        tile[j][threadIdx.x] = ib[(size_t)(c0 + j) * TT + t0 + threadIdx.x];
    __syncthreads();
    __nv_bfloat16* hb = hi + (size_t)b * TT * CC;
    __nv_bfloat16* lb = lo + (size_t)b * TT * CC;
    for (int j = threadIdx.y; j < 32; j += 8) {
        const float v = tile[threadIdx.x][j];
        const __nv_bfloat16 h = __float2bfloat16(v);
        const size_t o = (size_t)(t0 + j) * CC + c0 + threadIdx.x;
        hb[o] = h;
        lb[o] = __float2bfloat16(v - __bfloat162float(h));
    }
}

// ===========================================================================
// mma.sync split GEMM.
// MODE 0: bf16 3-term (A hi/lo, B hi/lo).  MODE 1: fp16 asym (A single, B hi/lo).
// EPI 1 = +residual -> fp32 Cout; EPI 2 = QKV attention-layout epilogue.
// All operand pointers passed as uint16_t* (raw 16-bit words).
// ===========================================================================
template <int MODE>
__device__ __forceinline__ void g_load_stage(
    uint32_t st, int kc,
    const uint16_t* __restrict__ Ahi, const uint16_t* __restrict__ Alo,
    const uint16_t* __restrict__ Bhi, const uint16_t* __restrict__ Blo,
    int m0, int n0, int tid)
{
    const uint32_t bOff = (MODE == 0) ? 2 * A_BYTES : A_BYTES;
    for (int i = tid; i < GM_MT * 4; i += 256) {
        const int r = i >> 2, c = i & 3;
        const uint32_t dst = st + (uint32_t)(r * PITCH + c * 8) * 2;
        const size_t g = (size_t)(m0 + r) * CC + kc + c * 8;
        cp16(dst, Ahi + g);
        if (MODE == 0) cp16(dst + A_BYTES, Alo + g);
    }
    for (int i = tid; i < GM_NT * 4; i += 256) {
        const int r = i >> 2, c = i & 3;
        const uint32_t dst = st + bOff + (uint32_t)(r * PITCH + c * 8) * 2;
        const size_t g = (size_t)(n0 + r) * CC + kc + c * 8;
        cp16(dst, Bhi + g);
        cp16(dst + B_BYTES, Blo + g);
    }
    cp_commit();
}

template <int EPI, int MODE>
__global__ void __launch_bounds__(256) hgemm(
    const uint16_t* __restrict__ Ahi, const uint16_t* __restrict__ Alo,
    const uint16_t* __restrict__ BhiAll, const uint16_t* __restrict__ BloAll,
    const float* __restrict__ Res, float* __restrict__ Cout, long outBatchStride)
{
    extern __shared__ char smem[];
    const uint32_t sbase = smem_u32(smem);
    const uint32_t stageB = (MODE == 0) ? STAGE0_BYTES : STAGE1_BYTES;

    const int tid = threadIdx.x;
    const int wid = tid >> 5;
    const int lane = tid & 31;
    const int b = blockIdx.z;
    const int m0 = blockIdx.y * GM_MT;
    const int n0 = blockIdx.x * GM_NT;
    const int wm = (wid >> 2) * 64;
    const int wn = (wid & 3) * 32;

    const uint16_t* Bhi = BhiAll + (size_t)b * TT * CC;
    const uint16_t* Blo = BloAll + (size_t)b * TT * CC;

    float acc[4][4][4];
#pragma unroll
    for (int i = 0; i < 4; i++)
#pragma unroll
        for (int j = 0; j < 4; j++)
#pragma unroll
            for (int r = 0; r < 4; r++) acc[i][j][r] = 0.0f;

    const int a_row = lane & 15;
    const int a_ksel = (lane >> 4) * 8;
    const int b4_row = lane & 7;
    const int b4_k = ((lane >> 3) & 1) * 8;
    const int b4_n = ((lane >> 4) & 1) * 8;

    g_load_stage<MODE>(sbase, 0, Ahi, Alo, Bhi, Blo, m0, n0, tid);

    for (int c = 0; c < NCHUNK; c++) {
        const uint32_t st = sbase + (uint32_t)(c & 1) * stageB;
        if (c + 1 < NCHUNK) {
            g_load_stage<MODE>(sbase + (uint32_t)((c + 1) & 1) * stageB,
                               (c + 1) * GM_KC, Ahi, Alo, Bhi, Blo, m0, n0, tid);
            asm volatile("cp.async.wait_group 1;\n" ::: "memory");
        } else {
            asm volatile("cp.async.wait_group 0;\n" ::: "memory");
        }
        __syncthreads();

        const uint32_t sAh = st;
        const uint32_t sAl = st + A_BYTES;  // MODE 0 only
        const uint32_t sBh = st + ((MODE == 0) ? 2 * A_BYTES : A_BYTES);
        const uint32_t sBl = sBh + B_BYTES;

#pragma unroll
        for (int kk = 0; kk < GM_KC; kk += 16) {
            uint32_t ah[4][4], al[4][4], bh[4][2], bl[4][2];
#pragma unroll
            for (int mi = 0; mi < 4; mi++) {
                const uint32_t off =
                    (uint32_t)((wm + mi * 16 + a_row) * PITCH + kk + a_ksel) * 2;
                ldmatrix_x4(ah[mi][0], ah[mi][1], ah[mi][2], ah[mi][3], sAh + off);
                if (MODE == 0)
                    ldmatrix_x4(al[mi][0], al[mi][1], al[mi][2], al[mi][3], sAl + off);
            }
#pragma unroll
            for (int p = 0; p < 2; p++) {
                const uint32_t off =
                    (uint32_t)((wn + p * 16 + b4_n + b4_row) * PITCH + kk + b4_k) * 2;
                ldmatrix_x4(bh[2 * p][0], bh[2 * p][1], bh[2 * p + 1][0],
                            bh[2 * p + 1][1], sBh + off);
                ldmatrix_x4(bl[2 * p][0], bl[2 * p][1], bl[2 * p + 1][0],
                            bl[2 * p + 1][1], sBl + off);
            }
#pragma unroll
            for (int mi = 0; mi < 4; mi++)
#pragma unroll
                for (int nj = 0; nj < 4; nj++) {
                    float* a = acc[mi][nj];
                    if (MODE == 0) {
                        mma_bf16(a, ah[mi][0], ah[mi][1], ah[mi][2], ah[mi][3],
                                 bh[nj][0], bh[nj][1]);
                        mma_bf16(a, ah[mi][0], ah[mi][1], ah[mi][2], ah[mi][3],
                                 bl[nj][0], bl[nj][1]);
                        mma_bf16(a, al[mi][0], al[mi][1], al[mi][2], al[mi][3],
                                 bh[nj][0], bh[nj][1]);
                    } else {
                        mma_f16(a, ah[mi][0], ah[mi][1], ah[mi][2], ah[mi][3],
                                bh[nj][0], bh[nj][1]);
                        mma_f16(a, ah[mi][0], ah[mi][1], ah[mi][2], ah[mi][3],
                                bl[nj][0], bl[nj][1]);
                    }
                }
        }
        __syncthreads();
    }

    const int er = lane >> 2;
    const int ec = (lane & 3) * 2;

    if (EPI == 1) {
        float* Cb = Cout + (size_t)b * outBatchStride;
        const float* Rb = Res + (size_t)b * CC * TT;
#pragma unroll
        for (int mi = 0; mi < 4; mi++)
#pragma unroll
            for (int nj = 0; nj < 4; nj++) {
                const int m = m0 + wm + mi * 16 + er;
                const int n = n0 + wn + nj * 8 + ec;
                float2 v0 = make_float2(acc[mi][nj][0], acc[mi][nj][1]);
                float2 v1 = make_float2(acc[mi][nj][2], acc[mi][nj][3]);
                const float2 r0 = *(const float2*)(Rb + (size_t)m * TT + n);
                const float2 r1 = *(const float2*)(Rb + (size_t)(m + 8) * TT + n);
                v0.x += r0.x; v0.y += r0.y;
                v1.x += r1.x; v1.y += r1.y;
                *(float2*)(Cb + (size_t)m * TT + n) = v0;
                *(float2*)(Cb + (size_t)(m + 8) * TT + n) = v1;
            }
    } else {
        if (m0 >= 2 * CC) {
            // V tile: fp16 hi/lo, [bh][d][t] layout
            const int chBase = m0 - 2 * CC;
            uint32_t* vhi = (uint32_t*)g_v_hi;
            uint32_t* vlo = (uint32_t*)g_v_lo;
#pragma unroll
            for (int mi = 0; mi < 4; mi++)
#pragma unroll
                for (int nj = 0; nj < 4; nj++) {
                    const int n = n0 + wn + nj * 8 + ec;
#pragma unroll
                    for (int rr = 0; rr < 2; rr++) {
                        const int ch = chBase + wm + mi * 16 + er + rr * 8;
                        const int bh = b * HH + (ch >> 6);
                        const int d = ch & 63;
                        uint32_t hi, lo;
                        split2h(acc[mi][nj][2 * rr], acc[mi][nj][2 * rr + 1], hi, lo);
                        const size_t idx = (((size_t)bh * DH + d) * TT + n) >> 1;
                        vhi[idx] = hi;
                        vlo[idx] = lo;
                    }
                }
        } else {
            // Q or K tile: bf16 hi/lo via smem transpose
            const bool isK = (m0 >= CC);
            const int chBase = isK ? (m0 - CC) : m0;
            const int h0 = chBase >> 6;
            float* stg = (float*)smem;
#pragma unroll
            for (int mi = 0; mi < 4; mi++)
#pragma unroll
                for (int nj = 0; nj < 4; nj++) {
                    const int m = wm + mi * 16 + er;
                    const int n = wn + nj * 8 + ec;
                    stg[n * 129 + m] = acc[mi][nj][0];
                    stg[(n + 1) * 129 + m] = acc[mi][nj][1];
                    stg[n * 129 + m + 8] = acc[mi][nj][2];
                    stg[(n + 1) * 129 + m + 8] = acc[mi][nj][3];
                }
            __syncthreads();
            uint32_t* dh = (uint32_t*)(isK ? g_kT_hi : g_qT_hi);
            uint32_t* dl = (uint32_t*)(isK ? g_kT_lo : g_qT_lo);
#pragma unroll
            for (int i = 0; i < 16; i++) {
                const int t = wid * 16 + i;
                const float* row = stg + t * 129;
#pragma unroll
                for (int half = 0; half < 2; half++) {
                    const float v0 = row[half * 64 + 2 * lane];
                    const float v1 = row[half * 64 + 2 * lane + 1];
                    uint32_t hi, lo;
                    split2(v0, v1, hi, lo);
                    const size_t idx =
                        ((size_t)(b * HH + h0 + half) * TT + n0 + t) * 32 + lane;
                    dh[idx] = hi;
                    dl[idx] = lo;
                }
            }
        }
    }
}

// ===========================================================================
// Tensor-core flash attention: QK bf16 3-term, PV fp16 (P single, V 2-term)
// ===========================================================================
__device__ __forceinline__ void attn_load_stage(uint32_t st, int bh, int k0, int tid)
{
    const __nv_bfloat16* kh = g_kT_hi + ((size_t)bh * TT + k0) * DH;
    const __nv_bfloat16* kl = g_kT_lo + ((size_t)bh * TT + k0) * DH;
    for (int i = tid; i < KT * 8; i += 256) {
        const int r = i >> 3, c = i & 7;
        const uint32_t d = st + (uint32_t)(r * QPITCH + c * 8) * 2;
        cp16(d, kh + (size_t)r * DH + c * 8);
        cp16(d + AK_B, kl + (size_t)r * DH + c * 8);
    }
    const __half* vh = g_v_hi + (size_t)bh * DH * TT + k0;
    const __half* vl = g_v_lo + (size_t)bh * DH * TT + k0;
    for (int i = tid; i < 64 * (KT / 8); i += 256) {
        const int r = i >> 3, c = i & 7;
        const uint32_t d = st + 2 * AK_B + (uint32_t)(r * QPITCH + c * 8) * 2;
        cp16(d, vh + (size_t)r * TT + c * 8);
        cp16(d + AK_B, vl + (size_t)r * TT + c * 8);
    }
}

__global__ void __launch_bounds__(256, 2) attn_mma()
{
    extern __shared__ char smem[];
    const uint32_t sb = smem_u32(smem);
    const uint32_t sQh = sb, sQl = sb + AQ_B;
    const uint32_t stage0 = sb + 2 * AQ_B;

    const int tid = threadIdx.x;
    const int wq = tid >> 5;
    const int lane = tid & 31;
    const int b = blockIdx.z, h = blockIdx.y;
    const int bh = b * HH + h;
    const int q0 = blockIdx.x * 128;

    {
        const __nv_bfloat16* qh = g_qT_hi + ((size_t)bh * TT + q0) * DH;
        const __nv_bfloat16* ql = g_qT_lo + ((size_t)bh * TT + q0) * DH;
        for (int i = tid; i < 128 * 8; i += 256) {
            const int r = i >> 3, c = i & 7;
            const uint32_t d = sQh + (uint32_t)(r * QPITCH + c * 8) * 2;
            cp16(d, qh + (size_t)r * DH + c * 8);
            cp16(d + AQ_B, ql + (size_t)r * DH + c * 8);
        }
        attn_load_stage(stage0, bh, 0, tid);
        cp_commit();
    }

    const int a_row = lane & 15;
    const int a_ksel = (lane >> 4) * 8;
    const int b4_row = lane & 7;
    const int b4_k = ((lane >> 3) & 1) * 8;
    const int b4_n = ((lane >> 4) & 1) * 8;

    uint32_t qfh[4][4], qfl[4][4];
    float O[8][4];
    float m0 = -__int_as_float(0x7f800000), m1 = m0;
    float l0 = 0.0f, l1 = 0.0f;
#pragma unroll
    for (int d = 0; d < 8; d++)
#pragma unroll
        for (int r = 0; r < 4; r++) O[d][r] = 0.0f;

    for (int kt = 0; kt < TT / KT; kt++) {
        const uint32_t stb = stage0 + (uint32_t)(kt & 1) * ASTAGE_B;
        if (kt + 1 < TT / KT) {
            attn_load_stage(stage0 + (uint32_t)((kt + 1) & 1) * ASTAGE_B,
                            bh, (kt + 1) * KT, tid);
            cp_commit();
            asm volatile("cp.async.wait_group 1;\n" ::: "memory");
        } else {
            asm volatile("cp.async.wait_group 0;\n" ::: "memory");
        }
        __syncthreads();

        if (kt == 0) {
#pragma unroll
            for (int ks = 0; ks < 4; ks++) {
                const uint32_t off =
                    (uint32_t)((wq * 16 + a_row) * QPITCH + ks * 16 + a_ksel) * 2;
                ldmatrix_x4(qfh[ks][0], qfh[ks][1], qfh[ks][2], qfh[ks][3], sQh + off);
                ldmatrix_x4(qfl[ks][0], qfl[ks][1], qfl[ks][2], qfl[ks][3], sQl + off);
            }
        }

        float S[8][4];
#pragma unroll
        for (int n = 0; n < 8; n++)
#pragma unroll
            for (int r = 0; r < 4; r++) S[n][r] = 0.0f;

        const uint32_t Kh = stb, Kl = stb + AK_B;
#pragma unroll
        for (int np = 0; np < 4; np++) {
#pragma unroll
            for (int ks = 0; ks < 4; ks++) {
                const uint32_t off =
                    (uint32_t)((np * 16 + b4_n + b4_row) * QPITCH + ks * 16 + b4_k) * 2;
                uint32_t kh0, kh1, kh2, kh3, kl0, kl1, kl2, kl3;
                ldmatrix_x4(kh0, kh1, kh2, kh3, Kh + off);
                ldmatrix_x4(kl0, kl1, kl2, kl3, Kl + off);
                mma_bf16(S[2 * np], qfh[ks][0], qfh[ks][1], qfh[ks][2], qfh[ks][3], kh0, kh1);
                mma_bf16(S[2 * np], qfh[ks][0], qfh[ks][1], qfh[ks][2], qfh[ks][3], kl0, kl1);
                mma_bf16(S[2 * np], qfl[ks][0], qfl[ks][1], qfl[ks][2], qfl[ks][3], kh0, kh1);
                mma_bf16(S[2 * np + 1], qfh[ks][0], qfh[ks][1], qfh[ks][2], qfh[ks][3], kh2, kh3);
                mma_bf16(S[2 * np + 1], qfh[ks][0], qfh[ks][1], qfh[ks][2], qfh[ks][3], kl2, kl3);
                mma_bf16(S[2 * np + 1], qfl[ks][0], qfl[ks][1], qfl[ks][2], qfl[ks][3], kh2, kh3);
            }
        }

        // online softmax
        float mx0 = -__int_as_float(0x7f800000), mx1 = mx0;
#pragma unroll
        for (int n = 0; n < 8; n++) {
            mx0 = fmaxf(mx0, fmaxf(S[n][0], S[n][1]));
            mx1 = fmaxf(mx1, fmaxf(S[n][2], S[n][3]));
        }
        mx0 = fmaxf(mx0, __shfl_xor_sync(0xffffffffu, mx0, 1));
        mx0 = fmaxf(mx0, __shfl_xor_sync(0xffffffffu, mx0, 2));
        mx1 = fmaxf(mx1, __shfl_xor_sync(0xffffffffu, mx1, 1));
        mx1 = fmaxf(mx1, __shfl_xor_sync(0xffffffffu, mx1, 2));
        const float mn0 = fmaxf(m0, mx0), mn1 = fmaxf(m1, mx1);
        const float al0 = __expf(m0 - mn0), al1 = __expf(m1 - mn1);
        float s0 = 0.0f, s1 = 0.0f;
#pragma unroll
        for (int n = 0; n < 8; n++) {
            S[n][0] = __expf(S[n][0] - mn0);
            S[n][1] = __expf(S[n][1] - mn0);
            S[n][2] = __expf(S[n][2] - mn1);
            S[n][3] = __expf(S[n][3] - mn1);
            s0 += S[n][0] + S[n][1];
            s1 += S[n][2] + S[n][3];
        }
        s0 += __shfl_xor_sync(0xffffffffu, s0, 1);
        s0 += __shfl_xor_sync(0xffffffffu, s0, 2);
        s1 += __shfl_xor_sync(0xffffffffu, s1, 1);
        s1 += __shfl_xor_sync(0xffffffffu, s1, 2);
        l0 = l0 * al0 + s0;
        l1 = l1 * al1 + s1;
        m0 = mn0;
        m1 = mn1;
#pragma unroll
        for (int d = 0; d < 8; d++) {
            O[d][0] *= al0; O[d][1] *= al0;
            O[d][2] *= al1; O[d][3] *= al1;
        }

        // O += P V  (P single fp16, V fp16 hi/lo)
        const uint32_t Vh = stb + 2 * AK_B, Vl = stb + 3 * AK_B;
#pragma unroll
        for (int u = 0; u < 4; u++) {
            uint32_t ph[4];
            ph[0] = cvt2h(S[2 * u][0], S[2 * u][1]);
            ph[1] = cvt2h(S[2 * u][2], S[2 * u][3]);
            ph[2] = cvt2h(S[2 * u + 1][0], S[2 * u + 1][1]);
            ph[3] = cvt2h(S[2 * u + 1][2], S[2 * u + 1][3]);
#pragma unroll
            for (int dp = 0; dp < 4; dp++) {
                const uint32_t off =
                    (uint32_t)((dp * 16 + b4_n + b4_row) * QPITCH + u * 16 + b4_k) * 2;
                uint32_t vh0, vh1, vh2, vh3, vl0, vl1, vl2, vl3;
                ldmatrix_x4(vh0, vh1, vh2, vh3, Vh + off);
                ldmatrix_x4(vl0, vl1, vl2, vl3, Vl + off);
                mma_f16(O[2 * dp], ph[0], ph[1], ph[2], ph[3], vh0, vh1);
                mma_f16(O[2 * dp], ph[0], ph[1], ph[2], ph[3], vl0, vl1);
                mma_f16(O[2 * dp + 1], ph[0], ph[1], ph[2], ph[3], vh2, vh3);
                mma_f16(O[2 * dp + 1], ph[0], ph[1], ph[2], ph[3], vl2, vl3);
            }
        }
        __syncthreads();
    }

    // epilogue: O/l, fp16 split, write to cT layout [b][t][c]
    const float r0 = 1.0f / l0, r1 = 1.0f / l1;
    const int row0 = q0 + wq * 16 + (lane >> 2);
    const size_t base0 = ((size_t)b * TT + row0) * CC + h * DH;
    const size_t base1 = base0 + (size_t)8 * CC;
#pragma unroll
    for (int dn = 0; dn < 8; dn++) {
        const int col = dn * 8 + 2 * (lane & 3);
        uint32_t hi, lo;
        split2h(O[dn][0] * r0, O[dn][1] * r0, hi, lo);
        *(uint32_t*)&g_cT_hi[base0 + col] = hi;
        *(uint32_t*)&g_cT_lo[base0 + col] = lo;
        split2h(O[dn][2] * r1, O[dn][3] * r1, hi, lo);
        *(uint32_t*)&g_cT_hi[base1 + col] = hi;
        *(uint32_t*)&g_cT_lo[base1 + col] = lo;
    }
}

// ===========================================================================
// LayerNorm
// ===========================================================================
__global__ void __launch_bounds__(256) ln_kernel(
    const float* __restrict__ gamma, const float* __restrict__ beta,
    float* __restrict__ out)
{
    const int tx = threadIdx.x, ty = threadIdx.y;
    const int b = blockIdx.y;
    const int t = blockIdx.x * 16 + tx;
    const float* yb = g_y + (long)b * CC * TT;

    float s = 0.0f, s2 = 0.0f;
    for (int c = ty; c < CC; c += 16) {
        const float v = yb[(long)c * TT + t];
        s += v;
        s2 += v * v;
    }
    __shared__ float rs[16][16], rq[16][16], mu_s[16], rstd_s[16];
    rs[ty][tx] = s;
    rq[ty][tx] = s2;
    __syncthreads();
    if (ty == 0) {
        float S = 0.0f, S2 = 0.0f;
#pragma unroll
        for (int k = 0; k < 16; k++) { S += rs[k][tx]; S2 += rq[k][tx]; }
        const float mu = S * (1.0f / CC);
        const float var = S2 * (1.0f / CC) - mu * mu;
        mu_s[tx] = mu;
        rstd_s[tx] = rsqrtf(var + LN_EPS);
    }
    __syncthreads();
    const float mu = mu_s[tx], rstd = rstd_s[tx];
    float* ob = out + (long)b * CC * TT;
    for (int c = ty; c < CC; c += 16) {
        const float v = yb[(long)c * TT + t];
        ob[(long)c * TT + t] = (v - mu) * rstd * gamma[c] + beta[c];
    }
}

// ===========================================================================
extern "C" void kernel_launch(void* const* d_in, const int* in_sizes, int n_in,
                              void* d_out, int out_size)
{
    const float* x     = (const float*)d_in[0];
    const float* wqkv  = (const float*)d_in[1];
    const float* wfc   = (const float*)d_in[2];
    const float* gamma = (const float*)d_in[3];
    const float* beta  = (const float*)d_in[4];
    float* out = (float*)d_out;

    float* y;
    cudaGetSymbolAddress((void**)&y, g_y);
    __nv_bfloat16 *wqh, *wql, *xth, *xtl;
    __half *wfh, *cth, *ctl;
    cudaGetSymbolAddress((void**)&wqh, g_wqkv_hi);
    cudaGetSymbolAddress((void**)&wql, g_wqkv_lo);
    cudaGetSymbolAddress((void**)&wfh, g_wfc_h);
    cudaGetSymbolAddress((void**)&xth, g_xT_hi);
    cudaGetSymbolAddress((void**)&xtl, g_xT_lo);
    cudaGetSymbolAddress((void**)&cth, g_cT_hi);
    cudaGetSymbolAddress((void**)&ctl, g_cT_lo);

    cudaFuncSetAttribute((const void*)hgemm<2, 0>, cudaFuncAttributeMaxDynamicSharedMemorySize, GEMM_SMEM0);
    cudaFuncSetAttribute((const void*)hgemm<1, 1>, cudaFuncAttributeMaxDynamicSharedMemorySize, GEMM_SMEM1);
    cudaFuncSetAttribute((const void*)attn_mma, cudaFuncAttributeMaxDynamicSharedMemorySize, ATTN_SMEM);

    // 0) precision-split conversions
    split_kernel<<<(3 * CC * CC + 255) / 256, 256>>>(wqkv, wqh, wql, 3 * CC * CC);
    cvtf16_kernel<<<(CC * CC + 255) / 256, 256>>>(wfc, wfh, CC * CC);
    tsplit_kernel<<<dim3(TT / 32, CC / 32, BB), dim3(32, 8)>>>(x, xth, xtl);

    // 1) QKV GEMM (bf16 3-term) with fused attention-layout epilogue
    hgemm<2, 0><<<dim3(TT / GM_NT, 3 * CC / GM_MT, BB), 256, GEMM_SMEM0>>>(
        (const uint16_t*)wqh, (const uint16_t*)wql,
        (const uint16_t*)xth, (const uint16_t*)xtl, nullptr, nullptr, 0);

    // 2) tensor-core flash attention -> g_cT fp16 hi/lo
    attn_mma<<<dim3(TT / 128, HH, BB), 256, ATTN_SMEM>>>();

    // 3) y = w_fc @ ctx + x (fp16 asym 2-term, fused residual)
    hgemm<1, 1><<<dim3(TT / GM_NT, CC / GM_MT, BB), 256, GEMM_SMEM1>>>(
        (const uint16_t*)wfh, nullptr,
        (const uint16_t*)cth, (const uint16_t*)ctl, x, y, (long)CC * TT);

    // 4) LayerNorm -> out
    ln_kernel<<<dim3(TT / 16, BB), dim3(16, 16)>>>(gamma, beta, out);
}

// round 10
// speedup vs baseline: 1.1736x; 1.0156x over previous
#include <cuda_runtime.h>
#include <cuda_bf16.h>
#include <cuda_fp16.h>
#include <cstdint>

#define BB 2
#define CC 1024
#define TT 2048
#define HH 16
#define DH 64
#define LN_EPS 1e-6f
#define LOG2E 1.44269504088896340736f

// ---- dense GEMM tiling (KC=32, 2-stage, 2 CTAs/SM) ----
#define GM_MT 128
#define GM_NT 128
#define GM_KC 32
#define NCHUNK (CC / GM_KC)            // 32
#define PITCH 40
#define A_BYTES (GM_MT * PITCH * 2)     // 10240
#define B_BYTES (GM_NT * PITCH * 2)     // 10240
// MODE 0 (bf16 3-term): A hi/lo + B hi/lo
#define STAGE0_BYTES (2 * A_BYTES + 2 * B_BYTES)  // 40960
#define GEMM_SMEM0 (2 * STAGE0_BYTES)             // 81920
// MODE 2 (fp16 asym: A hi/lo + B single)
#define STAGE2_BYTES (2 * A_BYTES + B_BYTES)      // 30720
#define GEMM_SMEM2 (2 * STAGE2_BYTES)             // 61440

// ---- attention tiling: kt-tile 64, 108KB smem, 2 CTAs/SM ----
#define QPITCH 72
#define KT 64
#define AQ_B (128 * QPITCH * 2)
#define AK_B (KT * QPITCH * 2)
#define ASTAGE_B (4 * AK_B)
#define ATTN_SMEM (2 * AQ_B + 2 * ASTAGE_B)      // 110592

// ---- scratch ----
__device__ float g_y[(size_t)BB * CC * TT];
__device__ float g_lnsum[(size_t)BB * TT];
__device__ float g_lnsq[(size_t)BB * TT];
__device__ __nv_bfloat16 g_wqkv_hi[3 * CC * CC], g_wqkv_lo[3 * CC * CC];
__device__ __half g_wfc_hi[CC * CC], g_wfc_lo[CC * CC];
__device__ __nv_bfloat16 g_xT_hi[(size_t)BB * TT * CC], g_xT_lo[(size_t)BB * TT * CC];
__device__ __half g_cT[(size_t)BB * TT * CC];
__device__ __nv_bfloat16 g_qT_hi[(size_t)BB * HH * TT * DH], g_qT_lo[(size_t)BB * HH * TT * DH];
__device__ __nv_bfloat16 g_kT_hi[(size_t)BB * HH * TT * DH], g_kT_lo[(size_t)BB * HH * TT * DH];
__device__ __half g_v_hi[(size_t)BB * HH * DH * TT], g_v_lo[(size_t)BB * HH * DH * TT];

// ===========================================================================
__device__ __forceinline__ uint32_t smem_u32(const void* p) {
    return (uint32_t)__cvta_generic_to_shared(p);
}
__device__ __forceinline__ void cp16(uint32_t dst, const void* src) {
    asm volatile("cp.async.cg.shared.global [%0], [%1], 16;\n" :: "r"(dst), "l"(src));
}
__device__ __forceinline__ void cp_commit() {
    asm volatile("cp.async.commit_group;\n" ::: "memory");
}
__device__ __forceinline__ void ldmatrix_x4(uint32_t& a0, uint32_t& a1, uint32_t& a2,
                                            uint32_t& a3, uint32_t addr) {
    asm volatile("ldmatrix.sync.aligned.m8n8.x4.shared.b16 {%0,%1,%2,%3}, [%4];"
                 : "=r"(a0), "=r"(a1), "=r"(a2), "=r"(a3) : "r"(addr));
}
__device__ __forceinline__ void mma_bf16(float* c,
                                         uint32_t a0, uint32_t a1, uint32_t a2, uint32_t a3,
                                         uint32_t b0, uint32_t b1) {
    asm volatile(
        "mma.sync.aligned.m16n8k16.row.col.f32.bf16.bf16.f32 "
        "{%0,%1,%2,%3}, {%4,%5,%6,%7}, {%8,%9}, {%0,%1,%2,%3};"
        : "+f"(c[0]), "+f"(c[1]), "+f"(c[2]), "+f"(c[3])
        : "r"(a0), "r"(a1), "r"(a2), "r"(a3), "r"(b0), "r"(b1));
}
__device__ __forceinline__ void mma_f16(float* c,
                                        uint32_t a0, uint32_t a1, uint32_t a2, uint32_t a3,
                                        uint32_t b0, uint32_t b1) {
    asm volatile(
        "mma.sync.aligned.m16n8k16.row.col.f32.f16.f16.f32 "
        "{%0,%1,%2,%3}, {%4,%5,%6,%7}, {%8,%9}, {%0,%1,%2,%3};"
        : "+f"(c[0]), "+f"(c[1]), "+f"(c[2]), "+f"(c[3])
        : "r"(a0), "r"(a1), "r"(a2), "r"(a3), "r"(b0), "r"(b1));
}
__device__ __forceinline__ uint32_t cvt2(float f0, float f1) {  // bf16x2
    uint32_t r;
    asm("cvt.rn.bf16x2.f32 %0, %1, %2;" : "=r"(r) : "f"(f1), "f"(f0));
    return r;
}
__device__ __forceinline__ void split2(float f0, float f1, uint32_t& hi, uint32_t& lo) {
    hi = cvt2(f0, f1);
    const float h0 = __uint_as_float(hi << 16);
    const float h1 = __uint_as_float(hi & 0xffff0000u);
    lo = cvt2(f0 - h0, f1 - h1);
}
__device__ __forceinline__ uint32_t cvt2h(float f0, float f1) {  // f16x2
    uint32_t r;
    asm("cvt.rn.f16x2.f32 %0, %1, %2;" : "=r"(r) : "f"(f1), "f"(f0));
    return r;
}
__device__ __forceinline__ void split2h(float f0, float f1, uint32_t& hi, uint32_t& lo) {
    hi = cvt2h(f0, f1);
    const float h0 = __half2float(__ushort_as_half((unsigned short)(hi & 0xffffu)));
    const float h1 = __half2float(__ushort_as_half((unsigned short)(hi >> 16)));
    lo = cvt2h(f0 - h0, f1 - h1);
}

// ===========================================================================
// conversions
// ===========================================================================
__global__ void __launch_bounds__(256) split_kernel(
    const float* __restrict__ in, __nv_bfloat16* __restrict__ hi,
    __nv_bfloat16* __restrict__ lo, int n)
{
    int i = blockIdx.x * 256 + threadIdx.x;
    if (i < n) {
        const float v = in[i];
        const __nv_bfloat16 h = __float2bfloat16(v);
        hi[i] = h;
        lo[i] = __float2bfloat16(v - __bfloat162float(h));
    }
}

__global__ void __launch_bounds__(256) splith_kernel(
    const float* __restrict__ in, __half* __restrict__ hi,
    __half* __restrict__ lo, int n)
{
    int i = blockIdx.x * 256 + threadIdx.x;
    if (i < n) {
        const float v = in[i];
        const __half h = __float2half_rn(v);
        hi[i] = h;
        lo[i] = __float2half_rn(v - __half2float(h));
    }
}

__global__ void __launch_bounds__(256) lnzero_kernel()
{
    int i = blockIdx.x * 256 + threadIdx.x;
    if (i < BB * TT) { g_lnsum[i] = 0.0f; g_lnsq[i] = 0.0f; }
}

__global__ void __launch_bounds__(256) tsplit_kernel(
    const float* __restrict__ in, __nv_bfloat16* __restrict__ hi,
    __nv_bfloat16* __restrict__ lo)
{
    __shared__ float tile[32][33];
    const int b = blockIdx.z;
    const int t0 = blockIdx.x * 32, c0 = blockIdx.y * 32;
    const float* ib = in + (size_t)b * CC * TT;
    for (int j = threadIdx.y; j < 32; j += 8)
        tile[j][threadIdx.x] = ib[(size_t)(c0 + j) * TT + t0 + threadIdx.x];
    __syncthreads();
    __nv_bfloat16* hb = hi + (size_t)b * TT * CC;
    __nv_bfloat16* lb = lo + (size_t)b * TT * CC;
    for (int j = threadIdx.y; j < 32; j += 8) {
        const float v = tile[threadIdx.x][j];
        const __nv_bfloat16 h = __float2bfloat16(v);
        const size_t o = (size_t)(t0 + j) * CC + c0 + threadIdx.x;
        hb[o] = h;
        lb[o] = __float2bfloat16(v - __bfloat162float(h));
    }
}

// ===========================================================================
// mma.sync split GEMM.
// MODE 0: bf16 3-term (A hi/lo, B hi/lo).  MODE 2: fp16 asym (A hi/lo, B single).
// EPI 1 = +residual -> fp32 Cout + fused LN stats; EPI 2 = QKV attention epi.
// ===========================================================================
template <int MODE>
__device__ __forceinline__ void g_load_stage(
    uint32_t st, int kc,
    const uint16_t* __restrict__ Ahi, const uint16_t* __restrict__ Alo,
    const uint16_t* __restrict__ Bhi, const uint16_t* __restrict__ Blo,
    int m0, int n0, int tid)
{
    for (int i = tid; i < GM_MT * 4; i += 256) {
        const int r = i >> 2, c = i & 3;
        const uint32_t dst = st + (uint32_t)(r * PITCH + c * 8) * 2;
        const size_t g = (size_t)(m0 + r) * CC + kc + c * 8;
        cp16(dst, Ahi + g);
        cp16(dst + A_BYTES, Alo + g);
    }
    for (int i = tid; i < GM_NT * 4; i += 256) {
        const int r = i >> 2, c = i & 3;
        const uint32_t dst = st + 2 * A_BYTES + (uint32_t)(r * PITCH + c * 8) * 2;
        const size_t g = (size_t)(n0 + r) * CC + kc + c * 8;
        cp16(dst, Bhi + g);
        if (MODE == 0) cp16(dst + B_BYTES, Blo + g);
    }
    cp_commit();
}

template <int EPI, int MODE>
__global__ void __launch_bounds__(256) hgemm(
    const uint16_t* __restrict__ Ahi, const uint16_t* __restrict__ Alo,
    const uint16_t* __restrict__ BhiAll, const uint16_t* __restrict__ BloAll,
    const float* __restrict__ Res, float* __restrict__ Cout, long outBatchStride)
{
    extern __shared__ char smem[];
    const uint32_t sbase = smem_u32(smem);
    const uint32_t stageB = (MODE == 0) ? STAGE0_BYTES : STAGE2_BYTES;

    const int tid = threadIdx.x;
    const int wid = tid >> 5;
    const int lane = tid & 31;
    const int b = blockIdx.z;
    const int m0 = blockIdx.y * GM_MT;
    const int n0 = blockIdx.x * GM_NT;
    const int wm = (wid >> 2) * 64;
    const int wn = (wid & 3) * 32;

    const uint16_t* Bhi = BhiAll + (size_t)b * TT * CC;
    const uint16_t* Blo = (MODE == 0) ? (BloAll + (size_t)b * TT * CC) : nullptr;

    float acc[4][4][4];
#pragma unroll
    for (int i = 0; i < 4; i++)
#pragma unroll
        for (int j = 0; j < 4; j++)
#pragma unroll
            for (int r = 0; r < 4; r++) acc[i][j][r] = 0.0f;

    const int a_row = lane & 15;
    const int a_ksel = (lane >> 4) * 8;
    const int b4_row = lane & 7;
    const int b4_k = ((lane >> 3) & 1) * 8;
    const int b4_n = ((lane >> 4) & 1) * 8;

    g_load_stage<MODE>(sbase, 0, Ahi, Alo, Bhi, Blo, m0, n0, tid);

    for (int c = 0; c < NCHUNK; c++) {
        const uint32_t st = sbase + (uint32_t)(c & 1) * stageB;
        if (c + 1 < NCHUNK) {
            g_load_stage<MODE>(sbase + (uint32_t)((c + 1) & 1) * stageB,
                               (c + 1) * GM_KC, Ahi, Alo, Bhi, Blo, m0, n0, tid);
            asm volatile("cp.async.wait_group 1;\n" ::: "memory");
        } else {
            asm volatile("cp.async.wait_group 0;\n" ::: "memory");
        }
        __syncthreads();

        const uint32_t sAh = st;
        const uint32_t sAl = st + A_BYTES;
        const uint32_t sBh = st + 2 * A_BYTES;
        const uint32_t sBl = sBh + B_BYTES;  // MODE 0 only

#pragma unroll
        for (int kk = 0; kk < GM_KC; kk += 16) {
            uint32_t ah[4][4], al[4][4], bh[4][2], bl[4][2];
#pragma unroll
            for (int mi = 0; mi < 4; mi++) {
                const uint32_t off =
                    (uint32_t)((wm + mi * 16 + a_row) * PITCH + kk + a_ksel) * 2;
                ldmatrix_x4(ah[mi][0], ah[mi][1], ah[mi][2], ah[mi][3], sAh + off);
                ldmatrix_x4(al[mi][0], al[mi][1], al[mi][2], al[mi][3], sAl + off);
            }
#pragma unroll
            for (int p = 0; p < 2; p++) {
                const uint32_t off =
                    (uint32_t)((wn + p * 16 + b4_n + b4_row) * PITCH + kk + b4_k) * 2;
                ldmatrix_x4(bh[2 * p][0], bh[2 * p][1], bh[2 * p + 1][0],
                            bh[2 * p + 1][1], sBh + off);
                if (MODE == 0)
                    ldmatrix_x4(bl[2 * p][0], bl[2 * p][1], bl[2 * p + 1][0],
                                bl[2 * p + 1][1], sBl + off);
            }
#pragma unroll
            for (int mi = 0; mi < 4; mi++)
#pragma unroll
                for (int nj = 0; nj < 4; nj++) {
                    float* a = acc[mi][nj];
                    if (MODE == 0) {
                        mma_bf16(a, ah[mi][0], ah[mi][1], ah[mi][2], ah[mi][3],
                                 bh[nj][0], bh[nj][1]);
                        mma_bf16(a, ah[mi][0], ah[mi][1], ah[mi][2], ah[mi][3],
                                 bl[nj][0], bl[nj][1]);
                        mma_bf16(a, al[mi][0], al[mi][1], al[mi][2], al[mi][3],
                                 bh[nj][0], bh[nj][1]);
                    } else {
                        mma_f16(a, ah[mi][0], ah[mi][1], ah[mi][2], ah[mi][3],
                                bh[nj][0], bh[nj][1]);
                        mma_f16(a, al[mi][0], al[mi][1], al[mi][2], al[mi][3],
                                bh[nj][0], bh[nj][1]);
                    }
                }
        }
        __syncthreads();
    }

    const int er = lane >> 2;
    const int ec = (lane & 3) * 2;

    if (EPI == 1) {
        // residual add + store + fused LayerNorm stats
        float* lns = (float*)smem;
        float* lnq = lns + 128;
        if (tid < 128) { lns[tid] = 0.0f; lnq[tid] = 0.0f; }
        __syncthreads();

        float cs[8], cq[8];
#pragma unroll
        for (int i = 0; i < 8; i++) { cs[i] = 0.0f; cq[i] = 0.0f; }

        float* Cb = Cout + (size_t)b * outBatchStride;
        const float* Rb = Res + (size_t)b * CC * TT;
#pragma unroll
        for (int mi = 0; mi < 4; mi++)
#pragma unroll
            for (int nj = 0; nj < 4; nj++) {
                const int m = m0 + wm + mi * 16 + er;
                const int n = n0 + wn + nj * 8 + ec;
                float2 v0 = make_float2(acc[mi][nj][0], acc[mi][nj][1]);
                float2 v1 = make_float2(acc[mi][nj][2], acc[mi][nj][3]);
                const float2 r0 = *(const float2*)(Rb + (size_t)m * TT + n);
                const float2 r1 = *(const float2*)(Rb + (size_t)(m + 8) * TT + n);
                v0.x += r0.x; v0.y += r0.y;
                v1.x += r1.x; v1.y += r1.y;
                *(float2*)(Cb + (size_t)m * TT + n) = v0;
                *(float2*)(Cb + (size_t)(m + 8) * TT + n) = v1;
                cs[nj * 2 + 0] += v0.x + v1.x;
                cq[nj * 2 + 0] += v0.x * v0.x + v1.x * v1.x;
                cs[nj * 2 + 1] += v0.y + v1.y;
                cq[nj * 2 + 1] += v0.y * v0.y + v1.y * v1.y;
            }
#pragma unroll
        for (int ci = 0; ci < 8; ci++) {
            const int col = wn + (ci >> 1) * 8 + ec + (ci & 1);
            atomicAdd(&lns[col], cs[ci]);
            atomicAdd(&lnq[col], cq[ci]);
        }
        __syncthreads();
        if (tid < 128) {
            atomicAdd(&g_lnsum[(size_t)b * TT + n0 + tid], lns[tid]);
            atomicAdd(&g_lnsq[(size_t)b * TT + n0 + tid], lnq[tid]);
        }
    } else {
        // EPI == 2: QKV epilogue, write attention operand layouts directly
        if (m0 >= 2 * CC) {
            const int chBase = m0 - 2 * CC;
            uint32_t* vhi = (uint32_t*)g_v_hi;
            uint32_t* vlo = (uint32_t*)g_v_lo;
#pragma unroll
            for (int mi = 0; mi < 4; mi++)
#pragma unroll
                for (int nj = 0; nj < 4; nj++) {
                    const int n = n0 + wn + nj * 8 + ec;
#pragma unroll
                    for (int rr = 0; rr < 2; rr++) {
                        const int ch = chBase + wm + mi * 16 + er + rr * 8;
                        const int bh = b * HH + (ch >> 6);
                        const int d = ch & 63;
                        uint32_t hi, lo;
                        split2h(acc[mi][nj][2 * rr], acc[mi][nj][2 * rr + 1], hi, lo);
                        const size_t idx = (((size_t)bh * DH + d) * TT + n) >> 1;
                        vhi[idx] = hi;
                        vlo[idx] = lo;
                    }
                }
        } else {
            const bool isK = (m0 >= CC);
            const float qscale = isK ? 1.0f : LOG2E;  // pre-scale Q for exp2 softmax
            const int chBase = isK ? (m0 - CC) : m0;
            const int h0 = chBase >> 6;
            float* stg = (float*)smem;
#pragma unroll
            for (int mi = 0; mi < 4; mi++)
#pragma unroll
                for (int nj = 0; nj < 4; nj++) {
                    const int m = wm + mi * 16 + er;
                    const int n = wn + nj * 8 + ec;
                    stg[n * 129 + m] = acc[mi][nj][0];
                    stg[(n + 1) * 129 + m] = acc[mi][nj][1];
                    stg[n * 129 + m + 8] = acc[mi][nj][2];
                    stg[(n + 1) * 129 + m + 8] = acc[mi][nj][3];
                }
            __syncthreads();
            uint32_t* dh = (uint32_t*)(isK ? g_kT_hi : g_qT_hi);
            uint32_t* dl = (uint32_t*)(isK ? g_kT_lo : g_qT_lo);
#pragma unroll
            for (int i = 0; i < 16; i++) {
                const int t = wid * 16 + i;
                const float* row = stg + t * 129;
#pragma unroll
                for (int half = 0; half < 2; half++) {
                    const float v0 = row[half * 64 + 2 * lane] * qscale;
                    const float v1 = row[half * 64 + 2 * lane + 1] * qscale;
                    uint32_t hi, lo;
                    split2(v0, v1, hi, lo);
                    const size_t idx =
                        ((size_t)(b * HH + h0 + half) * TT + n0 + t) * 32 + lane;
                    dh[idx] = hi;
                    dl[idx] = lo;
                }
            }
        }
    }
}

// ===========================================================================
// Tensor-core flash attention: QK bf16 3-term (Q pre-scaled by log2e),
// exp2 softmax, PV fp16 (P single, V 2-term), cT single-fp16 output.
// ===========================================================================
__device__ __forceinline__ void attn_load_stage(uint32_t st, int bh, int k0, int tid)
{
    const __nv_bfloat16* kh = g_kT_hi + ((size_t)bh * TT + k0) * DH;
    const __nv_bfloat16* kl = g_kT_lo + ((size_t)bh * TT + k0) * DH;
    for (int i = tid; i < KT * 8; i += 256) {
        const int r = i >> 3, c = i & 7;
        const uint32_t d = st + (uint32_t)(r * QPITCH + c * 8) * 2;
        cp16(d, kh + (size_t)r * DH + c * 8);
        cp16(d + AK_B, kl + (size_t)r * DH + c * 8);
    }
    const __half* vh = g_v_hi + (size_t)bh * DH * TT + k0;
    const __half* vl = g_v_lo + (size_t)bh * DH * TT + k0;
    for (int i = tid; i < 64 * (KT / 8); i += 256) {
        const int r = i >> 3, c = i & 7;
        const uint32_t d = st + 2 * AK_B + (uint32_t)(r * QPITCH + c * 8) * 2;
        cp16(d, vh + (size_t)r * TT + c * 8);
        cp16(d + AK_B, vl + (size_t)r * TT + c * 8);
    }
}

__global__ void __launch_bounds__(256, 2) attn_mma()
{
    extern __shared__ char smem[];
    const uint32_t sb = smem_u32(smem);
    const uint32_t sQh = sb, sQl = sb + AQ_B;
    const uint32_t stage0 = sb + 2 * AQ_B;

    const int tid = threadIdx.x;
    const int wq = tid >> 5;
    const int lane = tid & 31;
    const int b = blockIdx.z, h = blockIdx.y;
    const int bh = b * HH + h;
    const int q0 = blockIdx.x * 128;

    {
        const __nv_bfloat16* qh = g_qT_hi + ((size_t)bh * TT + q0) * DH;
        const __nv_bfloat16* ql = g_qT_lo + ((size_t)bh * TT + q0) * DH;
        for (int i = tid; i < 128 * 8; i += 256) {
            const int r = i >> 3, c = i & 7;
            const uint32_t d = sQh + (uint32_t)(r * QPITCH + c * 8) * 2;
            cp16(d, qh + (size_t)r * DH + c * 8);
            cp16(d + AQ_B, ql + (size_t)r * DH + c * 8);
        }
        attn_load_stage(stage0, bh, 0, tid);
        cp_commit();
    }

    const int a_row = lane & 15;
    const int a_ksel = (lane >> 4) * 8;
    const int b4_row = lane & 7;
    const int b4_k = ((lane >> 3) & 1) * 8;
    const int b4_n = ((lane >> 4) & 1) * 8;

    uint32_t qfh[4][4], qfl[4][4];
    float O[8][4];
    float m0 = -__int_as_float(0x7f800000), m1 = m0;
    float l0 = 0.0f, l1 = 0.0f;
#pragma unroll
    for (int d = 0; d < 8; d++)
#pragma unroll
        for (int r = 0; r < 4; r++) O[d][r] = 0.0f;

    for (int kt = 0; kt < TT / KT; kt++) {
        const uint32_t stb = stage0 + (uint32_t)(kt & 1) * ASTAGE_B;
        if (kt + 1 < TT / KT) {
            attn_load_stage(stage0 + (uint32_t)((kt + 1) & 1) * ASTAGE_B,
                            bh, (kt + 1) * KT, tid);
            cp_commit();
            asm volatile("cp.async.wait_group 1;\n" ::: "memory");
        } else {
            asm volatile("cp.async.wait_group 0;\n" ::: "memory");
        }
        __syncthreads();

        if (kt == 0) {
#pragma unroll
            for (int ks = 0; ks < 4; ks++) {
                const uint32_t off =
                    (uint32_t)((wq * 16 + a_row) * QPITCH + ks * 16 + a_ksel) * 2;
                ldmatrix_x4(qfh[ks][0], qfh[ks][1], qfh[ks][2], qfh[ks][3], sQh + off);
                ldmatrix_x4(qfl[ks][0], qfl[ks][1], qfl[ks][2], qfl[ks][3], sQl + off);
            }
        }

        float S[8][4];
#pragma unroll
        for (int n = 0; n < 8; n++)
#pragma unroll
            for (int r = 0; r < 4; r++) S[n][r] = 0.0f;

        const uint32_t Kh = stb, Kl = stb + AK_B;
#pragma unroll
        for (int np = 0; np < 4; np++) {
#pragma unroll
            for (int ks = 0; ks < 4; ks++) {
                const uint32_t off =
                    (uint32_t)((np * 16 + b4_n + b4_row) * QPITCH + ks * 16 + b4_k) * 2;
                uint32_t kh0, kh1, kh2, kh3, kl0, kl1, kl2, kl3;
                ldmatrix_x4(kh0, kh1, kh2, kh3, Kh + off);
                ldmatrix_x4(kl0, kl1, kl2, kl3, Kl + off);
                mma_bf16(S[2 * np], qfh[ks][0], qfh[ks][1], qfh[ks][2], qfh[ks][3], kh0, kh1);
                mma_bf16(S[2 * np], qfh[ks][0], qfh[ks][1], qfh[ks][2], qfh[ks][3], kl0, kl1);
                mma_bf16(S[2 * np], qfl[ks][0], qfl[ks][1], qfl[ks][2], qfl[ks][3], kh0, kh1);
                mma_bf16(S[2 * np + 1], qfh[ks][0], qfh[ks][1], qfh[ks][2], qfh[ks][3], kh2, kh3);
                mma_bf16(S[2 * np + 1], qfh[ks][0], qfh[ks][1], qfh[ks][2], qfh[ks][3], kl2, kl3);
                mma_bf16(S[2 * np + 1], qfl[ks][0], qfl[ks][1], qfl[ks][2], qfl[ks][3], kh2, kh3);
            }
        }

        // online softmax (log2 domain; Q pre-scaled by log2e)
        float mx0 = -__int_as_float(0x7f800000), mx1 = mx0;
#pragma unroll
        for (int n = 0; n < 8; n++) {
            mx0 = fmaxf(mx0, fmaxf(S[n][0], S[n][1]));
            mx1 = fmaxf(mx1, fmaxf(S[n][2], S[n][3]));
        }
        mx0 = fmaxf(mx0, __shfl_xor_sync(0xffffffffu, mx0, 1));
        mx0 = fmaxf(mx0, __shfl_xor_sync(0xffffffffu, mx0, 2));
        mx1 = fmaxf(mx1, __shfl_xor_sync(0xffffffffu, mx1, 1));
        mx1 = fmaxf(mx1, __shfl_xor_sync(0xffffffffu, mx1, 2));
        const float mn0 = fmaxf(m0, mx0), mn1 = fmaxf(m1, mx1);
        const float al0 = exp2f(m0 - mn0), al1 = exp2f(m1 - mn1);
        float s0 = 0.0f, s1 = 0.0f;
#pragma unroll
        for (int n = 0; n < 8; n++) {
            S[n][0] = exp2f(S[n][0] - mn0);
            S[n][1] = exp2f(S[n][1] - mn0);
            S[n][2] = exp2f(S[n][2] - mn1);
            S[n][3] = exp2f(S[n][3] - mn1);
            s0 += S[n][0] + S[n][1];
            s1 += S[n][2] + S[n][3];
        }
        s0 += __shfl_xor_sync(0xffffffffu, s0, 1);
        s0 += __shfl_xor_sync(0xffffffffu, s0, 2);
        s1 += __shfl_xor_sync(0xffffffffu, s1, 1);
        s1 += __shfl_xor_sync(0xffffffffu, s1, 2);
        l0 = l0 * al0 + s0;
        l1 = l1 * al1 + s1;
        m0 = mn0;
        m1 = mn1;
#pragma unroll
        for (int d = 0; d < 8; d++) {
            O[d][0] *= al0; O[d][1] *= al0;
            O[d][2] *= al1; O[d][3] *= al1;
        }

        // O += P V  (P single fp16, V fp16 hi/lo)
        const uint32_t Vh = stb + 2 * AK_B, Vl = stb + 3 * AK_B;
#pragma unroll
        for (int u = 0; u < 4; u++) {
            uint32_t ph[4];
            ph[0] = cvt2h(S[2 * u][0], S[2 * u][1]);
            ph[1] = cvt2h(S[2 * u][2], S[2 * u][3]);
            ph[2] = cvt2h(S[2 * u + 1][0], S[2 * u + 1][1]);
            ph[3] = cvt2h(S[2 * u + 1][2], S[2 * u + 1][3]);
#pragma unroll
            for (int dp = 0; dp < 4; dp++) {
                const uint32_t off =
                    (uint32_t)((dp * 16 + b4_n + b4_row) * QPITCH + u * 16 + b4_k) * 2;
                uint32_t vh0, vh1, vh2, vh3, vl0, vl1, vl2, vl3;
                ldmatrix_x4(vh0, vh1, vh2, vh3, Vh + off);
                ldmatrix_x4(vl0, vl1, vl2, vl3, Vl + off);
                mma_f16(O[2 * dp], ph[0], ph[1], ph[2], ph[3], vh0, vh1);
                mma_f16(O[2 * dp], ph[0], ph[1], ph[2], ph[3], vl0, vl1);
                mma_f16(O[2 * dp + 1], ph[0], ph[1], ph[2], ph[3], vh2, vh3);
                mma_f16(O[2 * dp + 1], ph[0], ph[1], ph[2], ph[3], vl2, vl3);
            }
        }
        __syncthreads();
    }

    // epilogue: O/l, single fp16 cT
    const float r0 = 1.0f / l0, r1 = 1.0f / l1;
    const int row0 = q0 + wq * 16 + (lane >> 2);
    const size_t base0 = ((size_t)b * TT + row0) * CC + h * DH;
    const size_t base1 = base0 + (size_t)8 * CC;
#pragma unroll
    for (int dn = 0; dn < 8; dn++) {
        const int col = dn * 8 + 2 * (lane & 3);
        *(uint32_t*)&g_cT[base0 + col] = cvt2h(O[dn][0] * r0, O[dn][1] * r0);
        *(uint32_t*)&g_cT[base1 + col] = cvt2h(O[dn][2] * r1, O[dn][3] * r1);
    }
}

// ===========================================================================
// LayerNorm: normalize-only pass (stats precomputed in proj epilogue)
// ===========================================================================
__global__ void __launch_bounds__(256) ln_kernel(
    const float* __restrict__ gamma, const float* __restrict__ beta,
    float* __restrict__ out)
{
    const int tx = threadIdx.x, ty = threadIdx.y;
    const int b = blockIdx.y;
    const int t = blockIdx.x * 16 + tx;

    const float s = g_lnsum[(size_t)b * TT + t];
    const float q = g_lnsq[(size_t)b * TT + t];
    const float mu = s * (1.0f / CC);
    const float rstd = rsqrtf(q * (1.0f / CC) - mu * mu + LN_EPS);

    const float* yb = g_y + (size_t)b * CC * TT;
    float* ob = out + (size_t)b * CC * TT;
    for (int c = ty; c < CC; c += 16) {
        const float v = yb[(size_t)c * TT + t];
        ob[(size_t)c * TT + t] = (v - mu) * rstd * gamma[c] + beta[c];
    }
}

// ===========================================================================
extern "C" void kernel_launch(void* const* d_in, const int* in_sizes, int n_in,
                              void* d_out, int out_size)
{
    const float* x     = (const float*)d_in[0];
    const float* wqkv  = (const float*)d_in[1];
    const float* wfc   = (const float*)d_in[2];
    const float* gamma = (const float*)d_in[3];
    const float* beta  = (const float*)d_in[4];
    float* out = (float*)d_out;

    float* y;
    cudaGetSymbolAddress((void**)&y, g_y);
    __nv_bfloat16 *wqh, *wql, *xth, *xtl;
    __half *wfh, *wfl, *ct;
    cudaGetSymbolAddress((void**)&wqh, g_wqkv_hi);
    cudaGetSymbolAddress((void**)&wql, g_wqkv_lo);
    cudaGetSymbolAddress((void**)&wfh, g_wfc_hi);
    cudaGetSymbolAddress((void**)&wfl, g_wfc_lo);
    cudaGetSymbolAddress((void**)&xth, g_xT_hi);
    cudaGetSymbolAddress((void**)&xtl, g_xT_lo);
    cudaGetSymbolAddress((void**)&ct, g_cT);

    cudaFuncSetAttribute((const void*)hgemm<2, 0>, cudaFuncAttributeMaxDynamicSharedMemorySize, GEMM_SMEM0);
    cudaFuncSetAttribute((const void*)hgemm<1, 2>, cudaFuncAttributeMaxDynamicSharedMemorySize, GEMM_SMEM2);
    cudaFuncSetAttribute((const void*)attn_mma, cudaFuncAttributeMaxDynamicSharedMemorySize, ATTN_SMEM);

    // 0) conversions + LN-stat zero
    split_kernel<<<(3 * CC * CC + 255) / 256, 256>>>(wqkv, wqh, wql, 3 * CC * CC);
    splith_kernel<<<(CC * CC + 255) / 256, 256>>>(wfc, wfh, wfl, CC * CC);
    tsplit_kernel<<<dim3(TT / 32, CC / 32, BB), dim3(32, 8)>>>(x, xth, xtl);
    lnzero_kernel<<<(BB * TT + 255) / 256, 256>>>();

    // 1) QKV GEMM (bf16 3-term) with fused attention-layout epilogue (Q pre-scaled)
    hgemm<2, 0><<<dim3(TT / GM_NT, 3 * CC / GM_MT, BB), 256, GEMM_SMEM0>>>(
        (const uint16_t*)wqh, (const uint16_t*)wql,
        (const uint16_t*)xth, (const uint16_t*)xtl, nullptr, nullptr, 0);

    // 2) tensor-core flash attention -> g_cT single fp16
    attn_mma<<<dim3(TT / 128, HH, BB), 256, ATTN_SMEM>>>();

    // 3) y = w_fc @ ctx + x (fp16 asym: W hi/lo x ctx single) + fused LN stats
    hgemm<1, 2><<<dim3(TT / GM_NT, CC / GM_MT, BB), 256, GEMM_SMEM2>>>(
        (const uint16_t*)wfh, (const uint16_t*)wfl,
        (const uint16_t*)ct, nullptr, x, y, (long)CC * TT);

    // 4) LayerNorm normalize-only -> out
    ln_kernel<<<dim3(TT / 16, BB), dim3(16, 16)>>>(gamma, beta, out);
}

// round 11
// speedup vs baseline: 1.3053x; 1.1122x over previous
#include <cuda_runtime.h>
#include <cuda_bf16.h>
#include <cuda_fp16.h>
#include <cstdint>

#define BB 2
#define CC 1024
#define TT 2048
#define HH 16
#define DH 64
#define LN_EPS 1e-6f
#define LOG2E 1.44269504088896340736f

// ---- dense GEMM tiling (KC=32, 2-stage, 2 CTAs/SM) ----
#define GM_MT 128
#define GM_NT 128
#define GM_KC 32
#define NCHUNK (CC / GM_KC)            // 32
#define PITCH 40
#define A_BYTES (GM_MT * PITCH * 2)     // 10240
#define B_BYTES (GM_NT * PITCH * 2)     // 10240
// MODE 0 (bf16 3-term): A hi/lo + B hi/lo
#define STAGE0_BYTES (2 * A_BYTES + 2 * B_BYTES)  // 40960
#define GEMM_SMEM0 (2 * STAGE0_BYTES)             // 81920
// MODE 2 (fp16 asym: A hi/lo + B single)
#define STAGE2_BYTES (2 * A_BYTES + B_BYTES)      // 30720
#define GEMM_SMEM2 (2 * STAGE2_BYTES)             // 61440

// ---- attention tiling: kt-tile 64, V single fp16 -> 92KB smem, 2 CTAs/SM ----
#define QPITCH 72
#define KT 64
#define AQ_B (128 * QPITCH * 2)         // 18432
#define AK_B (KT * QPITCH * 2)          // 9216
#define ASTAGE_B (3 * AK_B)             // 27648 (K hi/lo + V single)
#define ATTN_SMEM (2 * AQ_B + 2 * ASTAGE_B)      // 92160

// ---- scratch ----
__device__ float g_y[(size_t)BB * CC * TT];
__device__ float g_lnsum[(size_t)BB * TT];
__device__ float g_lnsq[(size_t)BB * TT];
__device__ __nv_bfloat16 g_wqk_hi[2 * CC * CC], g_wqk_lo[2 * CC * CC];
__device__ __half g_wv_hi[CC * CC], g_wv_lo[CC * CC];
__device__ __half g_wfc_hi[CC * CC], g_wfc_lo[CC * CC];
__device__ __nv_bfloat16 g_xT_hi[(size_t)BB * TT * CC], g_xT_lo[(size_t)BB * TT * CC];
__device__ __half g_xT_h16[(size_t)BB * TT * CC];
__device__ __half g_cT[(size_t)BB * TT * CC];
__device__ __nv_bfloat16 g_qT_hi[(size_t)BB * HH * TT * DH], g_qT_lo[(size_t)BB * HH * TT * DH];
__device__ __nv_bfloat16 g_kT_hi[(size_t)BB * HH * TT * DH], g_kT_lo[(size_t)BB * HH * TT * DH];
__device__ __half g_v[(size_t)BB * HH * DH * TT];

// ===========================================================================
__device__ __forceinline__ uint32_t smem_u32(const void* p) {
    return (uint32_t)__cvta_generic_to_shared(p);
}
__device__ __forceinline__ void cp16(uint32_t dst, const void* src) {
    asm volatile("cp.async.cg.shared.global [%0], [%1], 16;\n" :: "r"(dst), "l"(src));
}
__device__ __forceinline__ void cp_commit() {
    asm volatile("cp.async.commit_group;\n" ::: "memory");
}
__device__ __forceinline__ void ldmatrix_x4(uint32_t& a0, uint32_t& a1, uint32_t& a2,
                                            uint32_t& a3, uint32_t addr) {
    asm volatile("ldmatrix.sync.aligned.m8n8.x4.shared.b16 {%0,%1,%2,%3}, [%4];"
                 : "=r"(a0), "=r"(a1), "=r"(a2), "=r"(a3) : "r"(addr));
}
__device__ __forceinline__ void mma_bf16(float* c,
                                         uint32_t a0, uint32_t a1, uint32_t a2, uint32_t a3,
                                         uint32_t b0, uint32_t b1) {
    asm volatile(
        "mma.sync.aligned.m16n8k16.row.col.f32.bf16.bf16.f32 "
        "{%0,%1,%2,%3}, {%4,%5,%6,%7}, {%8,%9}, {%0,%1,%2,%3};"
        : "+f"(c[0]), "+f"(c[1]), "+f"(c[2]), "+f"(c[3])
        : "r"(a0), "r"(a1), "r"(a2), "r"(a3), "r"(b0), "r"(b1));
}
__device__ __forceinline__ void mma_f16(float* c,
                                        uint32_t a0, uint32_t a1, uint32_t a2, uint32_t a3,
                                        uint32_t b0, uint32_t b1) {
    asm volatile(
        "mma.sync.aligned.m16n8k16.row.col.f32.f16.f16.f32 "
        "{%0,%1,%2,%3}, {%4,%5,%6,%7}, {%8,%9}, {%0,%1,%2,%3};"
        : "+f"(c[0]), "+f"(c[1]), "+f"(c[2]), "+f"(c[3])
        : "r"(a0), "r"(a1), "r"(a2), "r"(a3), "r"(b0), "r"(b1));
}
__device__ __forceinline__ uint32_t cvt2(float f0, float f1) {  // bf16x2
    uint32_t r;
    asm("cvt.rn.bf16x2.f32 %0, %1, %2;" : "=r"(r) : "f"(f1), "f"(f0));
    return r;
}
__device__ __forceinline__ void split2(float f0, float f1, uint32_t& hi, uint32_t& lo) {
    hi = cvt2(f0, f1);
    const float h0 = __uint_as_float(hi << 16);
    const float h1 = __uint_as_float(hi & 0xffff0000u);
    lo = cvt2(f0 - h0, f1 - h1);
}
__device__ __forceinline__ uint32_t cvt2h(float f0, float f1) {  // f16x2
    uint32_t r;
    asm("cvt.rn.f16x2.f32 %0, %1, %2;" : "=r"(r) : "f"(f1), "f"(f0));
    return r;
}

// ===========================================================================
// conversions
// ===========================================================================
__global__ void __launch_bounds__(256) split_kernel(
    const float* __restrict__ in, __nv_bfloat16* __restrict__ hi,
    __nv_bfloat16* __restrict__ lo, int n)
{
    int i = blockIdx.x * 256 + threadIdx.x;
    if (i < n) {
        const float v = in[i];
        const __nv_bfloat16 h = __float2bfloat16(v);
        hi[i] = h;
        lo[i] = __float2bfloat16(v - __bfloat162float(h));
    }
}

__global__ void __launch_bounds__(256) splith_kernel(
    const float* __restrict__ in, __half* __restrict__ hi,
    __half* __restrict__ lo, int n)
{
    int i = blockIdx.x * 256 + threadIdx.x;
    if (i < n) {
        const float v = in[i];
        const __half h = __float2half_rn(v);
        hi[i] = h;
        lo[i] = __float2half_rn(v - __half2float(h));
    }
}

__global__ void __launch_bounds__(256) lnzero_kernel()
{
    int i = blockIdx.x * 256 + threadIdx.x;
    if (i < BB * TT) { g_lnsum[i] = 0.0f; g_lnsq[i] = 0.0f; }
}

// x [C,T] fp32 -> xT [T,C] bf16 hi/lo + fp16 single
__global__ void __launch_bounds__(256) tsplit_kernel(
    const float* __restrict__ in, __nv_bfloat16* __restrict__ hi,
    __nv_bfloat16* __restrict__ lo, __half* __restrict__ h16)
{
    __shared__ float tile[32][33];
    const int b = blockIdx.z;
    const int t0 = blockIdx.x * 32, c0 = blockIdx.y * 32;
    const float* ib = in + (size_t)b * CC * TT;
    for (int j = threadIdx.y; j < 32; j += 8)
        tile[j][threadIdx.x] = ib[(size_t)(c0 + j) * TT + t0 + threadIdx.x];
    __syncthreads();
    __nv_bfloat16* hb = hi + (size_t)b * TT * CC;
    __nv_bfloat16* lb = lo + (size_t)b * TT * CC;
    __half* sb = h16 + (size_t)b * TT * CC;
    for (int j = threadIdx.y; j < 32; j += 8) {
        const float v = tile[threadIdx.x][j];
        const __nv_bfloat16 h = __float2bfloat16(v);
        const size_t o = (size_t)(t0 + j) * CC + c0 + threadIdx.x;
        hb[o] = h;
        lb[o] = __float2bfloat16(v - __bfloat162float(h));
        sb[o] = __float2half_rn(v);
    }
}

// ===========================================================================
// mma.sync split GEMM.
// MODE 0: bf16 3-term (A hi/lo, B hi/lo).  MODE 2: fp16 asym (A hi/lo, B single).
// EPI 1 = residual + LN stats; EPI 2 = Q/K attention epi; EPI 3 = V epi.
// ===========================================================================
template <int MODE>
__device__ __forceinline__ void g_load_stage(
    uint32_t st, int kc,
    const uint16_t* __restrict__ Ahi, const uint16_t* __restrict__ Alo,
    const uint16_t* __restrict__ Bhi, const uint16_t* __restrict__ Blo,
    int m0, int n0, int tid)
{
    for (int i = tid; i < GM_MT * 4; i += 256) {
        const int r = i >> 2, c = i & 3;
        const uint32_t dst = st + (uint32_t)(r * PITCH + c * 8) * 2;
        const size_t g = (size_t)(m0 + r) * CC + kc + c * 8;
        cp16(dst, Ahi + g);
        cp16(dst + A_BYTES, Alo + g);
    }
    for (int i = tid; i < GM_NT * 4; i += 256) {
        const int r = i >> 2, c = i & 3;
        const uint32_t dst = st + 2 * A_BYTES + (uint32_t)(r * PITCH + c * 8) * 2;
        const size_t g = (size_t)(n0 + r) * CC + kc + c * 8;
        cp16(dst, Bhi + g);
        if (MODE == 0) cp16(dst + B_BYTES, Blo + g);
    }
    cp_commit();
}

template <int EPI, int MODE>
__global__ void __launch_bounds__(256) hgemm(
    const uint16_t* __restrict__ Ahi, const uint16_t* __restrict__ Alo,
    const uint16_t* __restrict__ BhiAll, const uint16_t* __restrict__ BloAll,
    const float* __restrict__ Res, float* __restrict__ Cout, long outBatchStride)
{
    extern __shared__ char smem[];
    const uint32_t sbase = smem_u32(smem);
    const uint32_t stageB = (MODE == 0) ? STAGE0_BYTES : STAGE2_BYTES;

    const int tid = threadIdx.x;
    const int wid = tid >> 5;
    const int lane = tid & 31;
    const int b = blockIdx.z;
    const int m0 = blockIdx.y * GM_MT;
    const int n0 = blockIdx.x * GM_NT;
    const int wm = (wid >> 2) * 64;
    const int wn = (wid & 3) * 32;

    const uint16_t* Bhi = BhiAll + (size_t)b * TT * CC;
    const uint16_t* Blo = (MODE == 0) ? (BloAll + (size_t)b * TT * CC) : nullptr;

    float acc[4][4][4];
#pragma unroll
    for (int i = 0; i < 4; i++)
#pragma unroll
        for (int j = 0; j < 4; j++)
#pragma unroll
            for (int r = 0; r < 4; r++) acc[i][j][r] = 0.0f;

    const int a_row = lane & 15;
    const int a_ksel = (lane >> 4) * 8;
    const int b4_row = lane & 7;
    const int b4_k = ((lane >> 3) & 1) * 8;
    const int b4_n = ((lane >> 4) & 1) * 8;

    g_load_stage<MODE>(sbase, 0, Ahi, Alo, Bhi, Blo, m0, n0, tid);

    for (int c = 0; c < NCHUNK; c++) {
        const uint32_t st = sbase + (uint32_t)(c & 1) * stageB;
        if (c + 1 < NCHUNK) {
            g_load_stage<MODE>(sbase + (uint32_t)((c + 1) & 1) * stageB,
                               (c + 1) * GM_KC, Ahi, Alo, Bhi, Blo, m0, n0, tid);
            asm volatile("cp.async.wait_group 1;\n" ::: "memory");
        } else {
            asm volatile("cp.async.wait_group 0;\n" ::: "memory");
        }
        __syncthreads();

        const uint32_t sAh = st;
        const uint32_t sAl = st + A_BYTES;
        const uint32_t sBh = st + 2 * A_BYTES;
        const uint32_t sBl = sBh + B_BYTES;  // MODE 0 only

#pragma unroll
        for (int kk = 0; kk < GM_KC; kk += 16) {
            uint32_t ah[4][4], al[4][4], bh[4][2], bl[4][2];
#pragma unroll
            for (int mi = 0; mi < 4; mi++) {
                const uint32_t off =
                    (uint32_t)((wm + mi * 16 + a_row) * PITCH + kk + a_ksel) * 2;
                ldmatrix_x4(ah[mi][0], ah[mi][1], ah[mi][2], ah[mi][3], sAh + off);
                ldmatrix_x4(al[mi][0], al[mi][1], al[mi][2], al[mi][3], sAl + off);
            }
#pragma unroll
            for (int p = 0; p < 2; p++) {
                const uint32_t off =
                    (uint32_t)((wn + p * 16 + b4_n + b4_row) * PITCH + kk + b4_k) * 2;
                ldmatrix_x4(bh[2 * p][0], bh[2 * p][1], bh[2 * p + 1][0],
                            bh[2 * p + 1][1], sBh + off);
                if (MODE == 0)
                    ldmatrix_x4(bl[2 * p][0], bl[2 * p][1], bl[2 * p + 1][0],
                                bl[2 * p + 1][1], sBl + off);
            }
#pragma unroll
            for (int mi = 0; mi < 4; mi++)
#pragma unroll
                for (int nj = 0; nj < 4; nj++) {
                    float* a = acc[mi][nj];
                    if (MODE == 0) {
                        mma_bf16(a, ah[mi][0], ah[mi][1], ah[mi][2], ah[mi][3],
                                 bh[nj][0], bh[nj][1]);
                        mma_bf16(a, ah[mi][0], ah[mi][1], ah[mi][2], ah[mi][3],
                                 bl[nj][0], bl[nj][1]);
                        mma_bf16(a, al[mi][0], al[mi][1], al[mi][2], al[mi][3],
                                 bh[nj][0], bh[nj][1]);
                    } else {
                        mma_f16(a, ah[mi][0], ah[mi][1], ah[mi][2], ah[mi][3],
                                bh[nj][0], bh[nj][1]);
                        mma_f16(a, al[mi][0], al[mi][1], al[mi][2], al[mi][3],
                                bh[nj][0], bh[nj][1]);
                    }
                }
        }
        __syncthreads();
    }

    const int er = lane >> 2;
    const int ec = (lane & 3) * 2;

    if (EPI == 1) {
        // residual add + store + fused LayerNorm stats
        float* lns = (float*)smem;
        float* lnq = lns + 128;
        if (tid < 128) { lns[tid] = 0.0f; lnq[tid] = 0.0f; }
        __syncthreads();

        float cs[8], cq[8];
#pragma unroll
        for (int i = 0; i < 8; i++) { cs[i] = 0.0f; cq[i] = 0.0f; }

        float* Cb = Cout + (size_t)b * outBatchStride;
        const float* Rb = Res + (size_t)b * CC * TT;
#pragma unroll
        for (int mi = 0; mi < 4; mi++)
#pragma unroll
            for (int nj = 0; nj < 4; nj++) {
                const int m = m0 + wm + mi * 16 + er;
                const int n = n0 + wn + nj * 8 + ec;
                float2 v0 = make_float2(acc[mi][nj][0], acc[mi][nj][1]);
                float2 v1 = make_float2(acc[mi][nj][2], acc[mi][nj][3]);
                const float2 r0 = *(const float2*)(Rb + (size_t)m * TT + n);
                const float2 r1 = *(const float2*)(Rb + (size_t)(m + 8) * TT + n);
                v0.x += r0.x; v0.y += r0.y;
                v1.x += r1.x; v1.y += r1.y;
                *(float2*)(Cb + (size_t)m * TT + n) = v0;
                *(float2*)(Cb + (size_t)(m + 8) * TT + n) = v1;
                cs[nj * 2 + 0] += v0.x + v1.x;
                cq[nj * 2 + 0] += v0.x * v0.x + v1.x * v1.x;
                cs[nj * 2 + 1] += v0.y + v1.y;
                cq[nj * 2 + 1] += v0.y * v0.y + v1.y * v1.y;
            }
#pragma unroll
        for (int ci = 0; ci < 8; ci++) {
            const int col = wn + (ci >> 1) * 8 + ec + (ci & 1);
            atomicAdd(&lns[col], cs[ci]);
            atomicAdd(&lnq[col], cq[ci]);
        }
        __syncthreads();
        if (tid < 128) {
            atomicAdd(&g_lnsum[(size_t)b * TT + n0 + tid], lns[tid]);
            atomicAdd(&g_lnsq[(size_t)b * TT + n0 + tid], lnq[tid]);
        }
    } else if (EPI == 3) {
        // V epilogue: single fp16, [bh][d][t] layout (A = w_v, m0 in 0..CC)
        uint32_t* vv = (uint32_t*)g_v;
#pragma unroll
        for (int mi = 0; mi < 4; mi++)
#pragma unroll
            for (int nj = 0; nj < 4; nj++) {
                const int n = n0 + wn + nj * 8 + ec;
#pragma unroll
                for (int rr = 0; rr < 2; rr++) {
                    const int ch = m0 + wm + mi * 16 + er + rr * 8;
                    const int bh = b * HH + (ch >> 6);
                    const int d = ch & 63;
                    vv[(((size_t)bh * DH + d) * TT + n) >> 1] =
                        cvt2h(acc[mi][nj][2 * rr], acc[mi][nj][2 * rr + 1]);
                }
            }
    } else {
        // EPI == 2: Q/K epilogue (m0 in 0..2CC)
        const bool isK = (m0 >= CC);
        const float qscale = isK ? 1.0f : LOG2E;  // pre-scale Q for exp2 softmax
        const int chBase = isK ? (m0 - CC) : m0;
        const int h0 = chBase >> 6;
        float* stg = (float*)smem;
#pragma unroll
        for (int mi = 0; mi < 4; mi++)
#pragma unroll
            for (int nj = 0; nj < 4; nj++) {
                const int m = wm + mi * 16 + er;
                const int n = wn + nj * 8 + ec;
                stg[n * 129 + m] = acc[mi][nj][0];
                stg[(n + 1) * 129 + m] = acc[mi][nj][1];
                stg[n * 129 + m + 8] = acc[mi][nj][2];
                stg[(n + 1) * 129 + m + 8] = acc[mi][nj][3];
            }
        __syncthreads();
        uint32_t* dh = (uint32_t*)(isK ? g_kT_hi : g_qT_hi);
        uint32_t* dl = (uint32_t*)(isK ? g_kT_lo : g_qT_lo);
#pragma unroll
        for (int i = 0; i < 16; i++) {
            const int t = wid * 16 + i;
            const float* row = stg + t * 129;
#pragma unroll
            for (int half = 0; half < 2; half++) {
                const float v0 = row[half * 64 + 2 * lane] * qscale;
                const float v1 = row[half * 64 + 2 * lane + 1] * qscale;
                uint32_t hi, lo;
                split2(v0, v1, hi, lo);
                const size_t idx =
                    ((size_t)(b * HH + h0 + half) * TT + n0 + t) * 32 + lane;
                dh[idx] = hi;
                dl[idx] = lo;
            }
        }
    }
}

// ===========================================================================
// Tensor-core flash attention: QK bf16 3-term (Q pre-scaled by log2e),
// exp2 softmax, PV fp16 single x single (1 mma), cT single-fp16 output.
// ===========================================================================
__device__ __forceinline__ void attn_load_stage(uint32_t st, int bh, int k0, int tid)
{
    const __nv_bfloat16* kh = g_kT_hi + ((size_t)bh * TT + k0) * DH;
    const __nv_bfloat16* kl = g_kT_lo + ((size_t)bh * TT + k0) * DH;
    for (int i = tid; i < KT * 8; i += 256) {
        const int r = i >> 3, c = i & 7;
        const uint32_t d = st + (uint32_t)(r * QPITCH + c * 8) * 2;
        cp16(d, kh + (size_t)r * DH + c * 8);
        cp16(d + AK_B, kl + (size_t)r * DH + c * 8);
    }
    const __half* vp = g_v + (size_t)bh * DH * TT + k0;
    for (int i = tid; i < 64 * (KT / 8); i += 256) {
        const int r = i >> 3, c = i & 7;
        const uint32_t d = st + 2 * AK_B + (uint32_t)(r * QPITCH + c * 8) * 2;
        cp16(d, vp + (size_t)r * TT + c * 8);
    }
}

__global__ void __launch_bounds__(256, 2) attn_mma()
{
    extern __shared__ char smem[];
    const uint32_t sb = smem_u32(smem);
    const uint32_t sQh = sb, sQl = sb + AQ_B;
    const uint32_t stage0 = sb + 2 * AQ_B;

    const int tid = threadIdx.x;
    const int wq = tid >> 5;
    const int lane = tid & 31;
    const int b = blockIdx.z, h = blockIdx.y;
    const int bh = b * HH + h;
    const int q0 = blockIdx.x * 128;

    {
        const __nv_bfloat16* qh = g_qT_hi + ((size_t)bh * TT + q0) * DH;
        const __nv_bfloat16* ql = g_qT_lo + ((size_t)bh * TT + q0) * DH;
        for (int i = tid; i < 128 * 8; i += 256) {
            const int r = i >> 3, c = i & 7;
            const uint32_t d = sQh + (uint32_t)(r * QPITCH + c * 8) * 2;
            cp16(d, qh + (size_t)r * DH + c * 8);
            cp16(d + AQ_B, ql + (size_t)r * DH + c * 8);
        }
        attn_load_stage(stage0, bh, 0, tid);
        cp_commit();
    }

    const int a_row = lane & 15;
    const int a_ksel = (lane >> 4) * 8;
    const int b4_row = lane & 7;
    const int b4_k = ((lane >> 3) & 1) * 8;
    const int b4_n = ((lane >> 4) & 1) * 8;

    uint32_t qfh[4][4], qfl[4][4];
    float O[8][4];
    float m0 = -__int_as_float(0x7f800000), m1 = m0;
    float l0 = 0.0f, l1 = 0.0f;
#pragma unroll
    for (int d = 0; d < 8; d++)
#pragma unroll
        for (int r = 0; r < 4; r++) O[d][r] = 0.0f;

    for (int kt = 0; kt < TT / KT; kt++) {
        const uint32_t stb = stage0 + (uint32_t)(kt & 1) * ASTAGE_B;
        if (kt + 1 < TT / KT) {
            attn_load_stage(stage0 + (uint32_t)((kt + 1) & 1) * ASTAGE_B,
                            bh, (kt + 1) * KT, tid);
            cp_commit();
            asm volatile("cp.async.wait_group 1;\n" ::: "memory");
        } else {
            asm volatile("cp.async.wait_group 0;\n" ::: "memory");
        }
        __syncthreads();

        if (kt == 0) {
#pragma unroll
            for (int ks = 0; ks < 4; ks++) {
                const uint32_t off =
                    (uint32_t)((wq * 16 + a_row) * QPITCH + ks * 16 + a_ksel) * 2;
                ldmatrix_x4(qfh[ks][0], qfh[ks][1], qfh[ks][2], qfh[ks][3], sQh + off);
                ldmatrix_x4(qfl[ks][0], qfl[ks][1], qfl[ks][2], qfl[ks][3], sQl + off);
            }
        }

        float S[8][4];
#pragma unroll
        for (int n = 0; n < 8; n++)
#pragma unroll
            for (int r = 0; r < 4; r++) S[n][r] = 0.0f;

        const uint32_t Kh = stb, Kl = stb + AK_B;
#pragma unroll
        for (int np = 0; np < 4; np++) {
#pragma unroll
            for (int ks = 0; ks < 4; ks++) {
                const uint32_t off =
                    (uint32_t)((np * 16 + b4_n + b4_row) * QPITCH + ks * 16 + b4_k) * 2;
                uint32_t kh0, kh1, kh2, kh3, kl0, kl1, kl2, kl3;
                ldmatrix_x4(kh0, kh1, kh2, kh3, Kh + off);
                ldmatrix_x4(kl0, kl1, kl2, kl3, Kl + off);
                mma_bf16(S[2 * np], qfh[ks][0], qfh[ks][1], qfh[ks][2], qfh[ks][3], kh0, kh1);
                mma_bf16(S[2 * np], qfh[ks][0], qfh[ks][1], qfh[ks][2], qfh[ks][3], kl0, kl1);
                mma_bf16(S[2 * np], qfl[ks][0], qfl[ks][1], qfl[ks][2], qfl[ks][3], kh0, kh1);
                mma_bf16(S[2 * np + 1], qfh[ks][0], qfh[ks][1], qfh[ks][2], qfh[ks][3], kh2, kh3);
                mma_bf16(S[2 * np + 1], qfh[ks][0], qfh[ks][1], qfh[ks][2], qfh[ks][3], kl2, kl3);
                mma_bf16(S[2 * np + 1], qfl[ks][0], qfl[ks][1], qfl[ks][2], qfl[ks][3], kh2, kh3);
            }
        }

        // online softmax (log2 domain)
        float mx0 = -__int_as_float(0x7f800000), mx1 = mx0;
#pragma unroll
        for (int n = 0; n < 8; n++) {
            mx0 = fmaxf(mx0, fmaxf(S[n][0], S[n][1]));
            mx1 = fmaxf(mx1, fmaxf(S[n][2], S[n][3]));
        }
        mx0 = fmaxf(mx0, __shfl_xor_sync(0xffffffffu, mx0, 1));
        mx0 = fmaxf(mx0, __shfl_xor_sync(0xffffffffu, mx0, 2));
        mx1 = fmaxf(mx1, __shfl_xor_sync(0xffffffffu, mx1, 1));
        mx1 = fmaxf(mx1, __shfl_xor_sync(0xffffffffu, mx1, 2));
        const float mn0 = fmaxf(m0, mx0), mn1 = fmaxf(m1, mx1);
        const float al0 = exp2f(m0 - mn0), al1 = exp2f(m1 - mn1);
        float s0 = 0.0f, s1 = 0.0f;
#pragma unroll
        for (int n = 0; n < 8; n++) {
            S[n][0] = exp2f(S[n][0] - mn0);
            S[n][1] = exp2f(S[n][1] - mn0);
            S[n][2] = exp2f(S[n][2] - mn1);
            S[n][3] = exp2f(S[n][3] - mn1);
            s0 += S[n][0] + S[n][1];
            s1 += S[n][2] + S[n][3];
        }
        s0 += __shfl_xor_sync(0xffffffffu, s0, 1);
        s0 += __shfl_xor_sync(0xffffffffu, s0, 2);
        s1 += __shfl_xor_sync(0xffffffffu, s1, 1);
        s1 += __shfl_xor_sync(0xffffffffu, s1, 2);
        l0 = l0 * al0 + s0;
        l1 = l1 * al1 + s1;
        m0 = mn0;
        m1 = mn1;
#pragma unroll
        for (int d = 0; d < 8; d++) {
            O[d][0] *= al0; O[d][1] *= al0;
            O[d][2] *= al1; O[d][3] *= al1;
        }

        // O += P V  (both single fp16: 1 mma per O tile)
        const uint32_t Vs = stb + 2 * AK_B;
#pragma unroll
        for (int u = 0; u < 4; u++) {
            uint32_t ph[4];
            ph[0] = cvt2h(S[2 * u][0], S[2 * u][1]);
            ph[1] = cvt2h(S[2 * u][2], S[2 * u][3]);
            ph[2] = cvt2h(S[2 * u + 1][0], S[2 * u + 1][1]);
            ph[3] = cvt2h(S[2 * u + 1][2], S[2 * u + 1][3]);
#pragma unroll
            for (int dp = 0; dp < 4; dp++) {
                const uint32_t off =
                    (uint32_t)((dp * 16 + b4_n + b4_row) * QPITCH + u * 16 + b4_k) * 2;
                uint32_t vh0, vh1, vh2, vh3;
                ldmatrix_x4(vh0, vh1, vh2, vh3, Vs + off);
                mma_f16(O[2 * dp], ph[0], ph[1], ph[2], ph[3], vh0, vh1);
                mma_f16(O[2 * dp + 1], ph[0], ph[1], ph[2], ph[3], vh2, vh3);
            }
        }
        __syncthreads();
    }

    // epilogue: O/l, single fp16 cT
    const float r0 = 1.0f / l0, r1 = 1.0f / l1;
    const int row0 = q0 + wq * 16 + (lane >> 2);
    const size_t base0 = ((size_t)b * TT + row0) * CC + h * DH;
    const size_t base1 = base0 + (size_t)8 * CC;
#pragma unroll
    for (int dn = 0; dn < 8; dn++) {
        const int col = dn * 8 + 2 * (lane & 3);
        *(uint32_t*)&g_cT[base0 + col] = cvt2h(O[dn][0] * r0, O[dn][1] * r0);
        *(uint32_t*)&g_cT[base1 + col] = cvt2h(O[dn][2] * r1, O[dn][3] * r1);
    }
}

// ===========================================================================
// LayerNorm: normalize-only
// ===========================================================================
__global__ void __launch_bounds__(256) ln_kernel(
    const float* __restrict__ gamma, const float* __restrict__ beta,
    float* __restrict__ out)
{
    const int tx = threadIdx.x, ty = threadIdx.y;
    const int b = blockIdx.y;
    const int t = blockIdx.x * 16 + tx;

    const float s = g_lnsum[(size_t)b * TT + t];
    const float q = g_lnsq[(size_t)b * TT + t];
    const float mu = s * (1.0f / CC);
    const float rstd = rsqrtf(q * (1.0f / CC) - mu * mu + LN_EPS);

    const float* yb = g_y + (size_t)b * CC * TT;
    float* ob = out + (size_t)b * CC * TT;
    for (int c = ty; c < CC; c += 16) {
        const float v = yb[(size_t)c * TT + t];
        ob[(size_t)c * TT + t] = (v - mu) * rstd * gamma[c] + beta[c];
    }
}

// ===========================================================================
extern "C" void kernel_launch(void* const* d_in, const int* in_sizes, int n_in,
                              void* d_out, int out_size)
{
    const float* x     = (const float*)d_in[0];
    const float* wqkv  = (const float*)d_in[1];
    const float* wfc   = (const float*)d_in[2];
    const float* gamma = (const float*)d_in[3];
    const float* beta  = (const float*)d_in[4];
    float* out = (float*)d_out;

    float* y;
    cudaGetSymbolAddress((void**)&y, g_y);
    __nv_bfloat16 *wqkh, *wqkl, *xth, *xtl;
    __half *wvh, *wvl, *wfh, *wfl, *xt16, *ct;
    cudaGetSymbolAddress((void**)&wqkh, g_wqk_hi);
    cudaGetSymbolAddress((void**)&wqkl, g_wqk_lo);
    cudaGetSymbolAddress((void**)&wvh, g_wv_hi);
    cudaGetSymbolAddress((void**)&wvl, g_wv_lo);
    cudaGetSymbolAddress((void**)&wfh, g_wfc_hi);
    cudaGetSymbolAddress((void**)&wfl, g_wfc_lo);
    cudaGetSymbolAddress((void**)&xth, g_xT_hi);
    cudaGetSymbolAddress((void**)&xtl, g_xT_lo);
    cudaGetSymbolAddress((void**)&xt16, g_xT_h16);
    cudaGetSymbolAddress((void**)&ct, g_cT);

    cudaFuncSetAttribute((const void*)hgemm<2, 0>, cudaFuncAttributeMaxDynamicSharedMemorySize, GEMM_SMEM0);
    cudaFuncSetAttribute((const void*)hgemm<3, 2>, cudaFuncAttributeMaxDynamicSharedMemorySize, GEMM_SMEM2);
    cudaFuncSetAttribute((const void*)hgemm<1, 2>, cudaFuncAttributeMaxDynamicSharedMemorySize, GEMM_SMEM2);
    cudaFuncSetAttribute((const void*)attn_mma, cudaFuncAttributeMaxDynamicSharedMemorySize, ATTN_SMEM);

    // 0) conversions + LN-stat zero
    split_kernel<<<(2 * CC * CC + 255) / 256, 256>>>(wqkv, wqkh, wqkl, 2 * CC * CC);
    splith_kernel<<<(CC * CC + 255) / 256, 256>>>(wqkv + 2 * CC * CC, wvh, wvl, CC * CC);
    splith_kernel<<<(CC * CC + 255) / 256, 256>>>(wfc, wfh, wfl, CC * CC);
    tsplit_kernel<<<dim3(TT / 32, CC / 32, BB), dim3(32, 8)>>>(x, xth, xtl, xt16);
    lnzero_kernel<<<(BB * TT + 255) / 256, 256>>>();

    // 1a) Q/K GEMM (bf16 3-term) with fused attention-layout epilogue
    hgemm<2, 0><<<dim3(TT / GM_NT, 2 * CC / GM_MT, BB), 256, GEMM_SMEM0>>>(
        (const uint16_t*)wqkh, (const uint16_t*)wqkl,
        (const uint16_t*)xth, (const uint16_t*)xtl, nullptr, nullptr, 0);

    // 1b) V GEMM (fp16 asym: w_v hi/lo x x single) -> g_v single fp16
    hgemm<3, 2><<<dim3(TT / GM_NT, CC / GM_MT, BB), 256, GEMM_SMEM2>>>(
        (const uint16_t*)wvh, (const uint16_t*)wvl,
        (const uint16_t*)xt16, nullptr, nullptr, nullptr, 0);

    // 2) tensor-core flash attention -> g_cT single fp16
    attn_mma<<<dim3(TT / 128, HH, BB), 256, ATTN_SMEM>>>();

    // 3) y = w_fc @ ctx + x (fp16 asym) + fused LN stats
    hgemm<1, 2><<<dim3(TT / GM_NT, CC / GM_MT, BB), 256, GEMM_SMEM2>>>(
        (const uint16_t*)wfh, (const uint16_t*)wfl,
        (const uint16_t*)ct, nullptr, x, y, (long)CC * TT);

    // 4) LayerNorm normalize-only -> out
    ln_kernel<<<dim3(TT / 16, BB), dim3(16, 16)>>>(gamma, beta, out);
}